// round 3
// baseline (speedup 1.0000x reference)
#include <cuda_runtime.h>
#include <math.h>

#define BB 2048
#define FF 64
#define DD 512
#define AA 512
#define HH 8
#define HD 64

// Scratch (allocation-free rule: __device__ globals). Layout [b, h, f, d].
__device__ float g_Qc[(size_t)BB * HH * FF * HD];
__device__ float g_Kc[(size_t)BB * HH * FF * HD];
__device__ float g_V [(size_t)BB * HH * FF * HD];

// ---------------------------------------------------------------------------
// Kernel 1: projection GEMM + bias + (optional) mean-centering over field axis.
// One block computes a 64(F) x 128(N) tile of X[b] @ W for one projection.
// Since the tile spans ALL F rows, the column mean is block-local.
// grid = (4 ntiles, 2048 batches, 3 projections {Q,K,V}), block = 128 threads.
// Thread microtile: 8 rows x 8 cols (8x16 thread grid).
// ---------------------------------------------------------------------------
__global__ __launch_bounds__(128) void proj_kernel(
    const float* __restrict__ Xq, const float* __restrict__ Xk, const float* __restrict__ Xv,
    const float* __restrict__ Wq, const float* __restrict__ Wk, const float* __restrict__ Wv,
    const float* __restrict__ bq, const float* __restrict__ bk, const float* __restrict__ bv)
{
    const int nt = blockIdx.x;          // n-tile: cols [nt*128, nt*128+128)
    const int b  = blockIdx.y;          // batch
    const int p  = blockIdx.z;          // 0=Q, 1=K, 2=V

    const float* X    = (p == 0) ? Xq : (p == 1) ? Xk : Xv;
    const float* W    = (p == 0) ? Wq : (p == 1) ? Wk : Wv;
    const float* bias = (p == 0) ? bq : (p == 1) ? bk : bv;
    float*       dst  = (p == 0) ? g_Qc : (p == 1) ? g_Kc : g_V;
    const bool center = (p < 2);        // Q and K are mean-centered; V is not

    __shared__ float As[16][68];        // X tile, transposed [k][m], padded
    __shared__ float Bs[16][128];       // W tile [k][n]
    __shared__ float red[8][128];       // column partial sums for centering
    __shared__ float means[128];

    const int tid = threadIdx.x;
    const int tx  = tid & 15;           // 0..15 (col group: 8 cols each)
    const int ty  = tid >> 4;           // 0..7  (row group: 8 rows each)
    const int n0  = nt * 128;

    float acc[8][8];
    #pragma unroll
    for (int i = 0; i < 8; i++)
        #pragma unroll
        for (int j = 0; j < 8; j++) acc[i][j] = 0.f;

    const float* Xb = X + (size_t)b * FF * DD;

    for (int k0 = 0; k0 < DD; k0 += 16) {
        // Load X tile (64x16) into As transposed: As[k][m]
        #pragma unroll
        for (int i = 0; i < 2; i++) {
            int idx = tid + i * 128;                    // 0..255
            int row = idx >> 2;                         // 0..63
            int kv  = idx & 3;                          // 0..3 (float4 along k)
            float4 v = *reinterpret_cast<const float4*>(Xb + row * DD + k0 + kv * 4);
            As[kv * 4 + 0][row] = v.x;
            As[kv * 4 + 1][row] = v.y;
            As[kv * 4 + 2][row] = v.z;
            As[kv * 4 + 3][row] = v.w;
        }
        // Load W tile (16x128) into Bs
        #pragma unroll
        for (int i = 0; i < 4; i++) {
            int idx = tid + i * 128;                    // 0..511
            int kk  = idx >> 5;                         // 0..15
            int nv  = idx & 31;                         // 0..31 (float4 along n)
            *reinterpret_cast<float4*>(&Bs[kk][nv * 4]) =
                *reinterpret_cast<const float4*>(W + (size_t)(k0 + kk) * AA + n0 + nv * 4);
        }
        __syncthreads();

        #pragma unroll
        for (int kk = 0; kk < 16; kk++) {
            float4 a0 = *reinterpret_cast<const float4*>(&As[kk][ty * 8]);
            float4 a1 = *reinterpret_cast<const float4*>(&As[kk][ty * 8 + 4]);
            float4 b0 = *reinterpret_cast<const float4*>(&Bs[kk][tx * 8]);
            float4 b1 = *reinterpret_cast<const float4*>(&Bs[kk][tx * 8 + 4]);
            float a[8] = {a0.x, a0.y, a0.z, a0.w, a1.x, a1.y, a1.z, a1.w};
            float bv_[8] = {b0.x, b0.y, b0.z, b0.w, b1.x, b1.y, b1.z, b1.w};
            #pragma unroll
            for (int i = 0; i < 8; i++)
                #pragma unroll
                for (int j = 0; j < 8; j++)
                    acc[i][j] = fmaf(a[i], bv_[j], acc[i][j]);
        }
        __syncthreads();
    }

    // Bias
    #pragma unroll
    for (int j = 0; j < 8; j++) {
        float bj = bias[n0 + tx * 8 + j];
        #pragma unroll
        for (int i = 0; i < 8; i++) acc[i][j] += bj;
    }

    // Mean-centering over the 64 field rows (block-local)
    if (center) {
        #pragma unroll
        for (int j = 0; j < 8; j++) {
            float s = 0.f;
            #pragma unroll
            for (int i = 0; i < 8; i++) s += acc[i][j];
            red[ty][tx * 8 + j] = s;
        }
        __syncthreads();
        if (tid < 128) {
            float s = 0.f;
            #pragma unroll
            for (int r = 0; r < 8; r++) s += red[r][tid];
            means[tid] = s * (1.f / 64.f);
        }
        __syncthreads();
        #pragma unroll
        for (int j = 0; j < 8; j++) {
            float m = means[tx * 8 + j];
            #pragma unroll
            for (int i = 0; i < 8; i++) acc[i][j] -= m;
        }
    }

    // Store to [b,h,f,d] layout. Column group (8 wide, 8-aligned) never
    // crosses a 64-col head boundary.
    const int ng0 = n0 + tx * 8;
    const int h   = ng0 >> 6;
    const int d0  = ng0 & 63;
    float* dstb = dst + ((size_t)b * HH + h) * FF * HD;
    #pragma unroll
    for (int i = 0; i < 8; i++) {
        int f = ty * 8 + i;
        float4 v0 = make_float4(acc[i][0], acc[i][1], acc[i][2], acc[i][3]);
        float4 v1 = make_float4(acc[i][4], acc[i][5], acc[i][6], acc[i][7]);
        *reinterpret_cast<float4*>(dstb + f * HD + d0)     = v0;
        *reinterpret_cast<float4*>(dstb + f * HD + d0 + 4) = v1;
    }
}

// ---------------------------------------------------------------------------
// Kernel 2: per-(b,h) attention.
//   S = Qc @ Kc^T (64x64), P = softmax_rows(S) + 1  (unary term == 1),
//   O = P @ V, out = relu(O + query), head h writes cols [h*64, h*64+64).
// grid = B*H blocks, 256 threads, dynamic smem = 3 * 64*68 floats.
// ---------------------------------------------------------------------------
__global__ __launch_bounds__(256) void attn_kernel(
    const float* __restrict__ query, float* __restrict__ out)
{
    const int bh = blockIdx.x;
    const int b  = bh >> 3;
    const int h  = bh & 7;

    extern __shared__ float sm[];
    float* Qs = sm;                 // 64 x 68 (also reused as V tile later)
    float* Ks = sm + 64 * 68;
    float* Ss = sm + 2 * 64 * 68;

    const int tid = threadIdx.x;
    const int tx  = tid & 15;       // 0..15
    const int ty  = tid >> 4;       // 0..15
    const int q0  = ty * 4;
    const int k0  = tx * 4;

    const float* Qg = g_Qc + (size_t)bh * FF * HD;
    const float* Kg = g_Kc + (size_t)bh * FF * HD;
    const float* Vg = g_V  + (size_t)bh * FF * HD;

    // Load Qc, Kc tiles (4096 floats each = 1024 float4, 4 per thread)
    #pragma unroll
    for (int i = 0; i < 4; i++) {
        int idx = tid + i * 256;    // 0..1023
        int f   = idx >> 4;
        int dv  = idx & 15;
        *reinterpret_cast<float4*>(Qs + f * 68 + dv * 4) =
            *reinterpret_cast<const float4*>(Qg + f * 64 + dv * 4);
        *reinterpret_cast<float4*>(Ks + f * 68 + dv * 4) =
            *reinterpret_cast<const float4*>(Kg + f * 64 + dv * 4);
    }
    __syncthreads();

    // S = Qc @ Kc^T : 4x4 microtile per thread
    float s[4][4];
    #pragma unroll
    for (int i = 0; i < 4; i++)
        #pragma unroll
        for (int j = 0; j < 4; j++) s[i][j] = 0.f;

    for (int d = 0; d < 64; d += 4) {
        float4 a[4], c[4];
        #pragma unroll
        for (int i = 0; i < 4; i++) a[i] = *reinterpret_cast<const float4*>(Qs + (q0 + i) * 68 + d);
        #pragma unroll
        for (int j = 0; j < 4; j++) c[j] = *reinterpret_cast<const float4*>(Ks + (k0 + j) * 68 + d);
        #pragma unroll
        for (int i = 0; i < 4; i++) {
            #pragma unroll
            for (int j = 0; j < 4; j++) {
                s[i][j] = fmaf(a[i].x, c[j].x, s[i][j]);
                s[i][j] = fmaf(a[i].y, c[j].y, s[i][j]);
                s[i][j] = fmaf(a[i].z, c[j].z, s[i][j]);
                s[i][j] = fmaf(a[i].w, c[j].w, s[i][j]);
            }
        }
    }
    #pragma unroll
    for (int i = 0; i < 4; i++)
        #pragma unroll
        for (int j = 0; j < 4; j++)
            Ss[(q0 + i) * 68 + (k0 + j)] = s[i][j];
    __syncthreads();

    // Overwrite Qs with the V tile (Qc no longer needed)
    #pragma unroll
    for (int i = 0; i < 4; i++) {
        int idx = tid + i * 256;
        int f   = idx >> 4;
        int dv  = idx & 15;
        *reinterpret_cast<float4*>(Qs + f * 68 + dv * 4) =
            *reinterpret_cast<const float4*>(Vg + f * 64 + dv * 4);
    }

    // Row softmax over k, then add the degenerate unary term (+1).
    // 4 threads per row, 16 entries each.
    {
        int q    = tid >> 2;
        int part = tid & 3;
        float* row = Ss + q * 68 + part * 16;
        float mx = -INFINITY;
        #pragma unroll
        for (int j = 0; j < 16; j++) mx = fmaxf(mx, row[j]);
        mx = fmaxf(mx, __shfl_xor_sync(0xFFFFFFFFu, mx, 1));
        mx = fmaxf(mx, __shfl_xor_sync(0xFFFFFFFFu, mx, 2));
        float e[16];
        float sum = 0.f;
        #pragma unroll
        for (int j = 0; j < 16; j++) { e[j] = expf(row[j] - mx); sum += e[j]; }
        sum += __shfl_xor_sync(0xFFFFFFFFu, sum, 1);
        sum += __shfl_xor_sync(0xFFFFFFFFu, sum, 2);
        float inv = 1.f / sum;
        #pragma unroll
        for (int j = 0; j < 16; j++) row[j] = e[j] * inv + 1.0f;
    }
    __syncthreads();

    // O = P @ V : 4x4 microtile per thread, d-cols = tx*4..tx*4+3
    float o[4][4];
    #pragma unroll
    for (int i = 0; i < 4; i++)
        #pragma unroll
        for (int j = 0; j < 4; j++) o[i][j] = 0.f;

    float* Vs = Qs;
    for (int k = 0; k < 64; k += 4) {
        float4 p[4], v[4];
        #pragma unroll
        for (int i = 0; i < 4; i++) p[i] = *reinterpret_cast<const float4*>(Ss + (q0 + i) * 68 + k);
        #pragma unroll
        for (int kk = 0; kk < 4; kk++) v[kk] = *reinterpret_cast<const float4*>(Vs + (k + kk) * 68 + tx * 4);
        #pragma unroll
        for (int i = 0; i < 4; i++) {
            o[i][0] = fmaf(p[i].x, v[0].x, o[i][0]); o[i][1] = fmaf(p[i].x, v[0].y, o[i][1]);
            o[i][2] = fmaf(p[i].x, v[0].z, o[i][2]); o[i][3] = fmaf(p[i].x, v[0].w, o[i][3]);
            o[i][0] = fmaf(p[i].y, v[1].x, o[i][0]); o[i][1] = fmaf(p[i].y, v[1].y, o[i][1]);
            o[i][2] = fmaf(p[i].y, v[1].z, o[i][2]); o[i][3] = fmaf(p[i].y, v[1].w, o[i][3]);
            o[i][0] = fmaf(p[i].z, v[2].x, o[i][0]); o[i][1] = fmaf(p[i].z, v[2].y, o[i][1]);
            o[i][2] = fmaf(p[i].z, v[2].z, o[i][2]); o[i][3] = fmaf(p[i].z, v[2].w, o[i][3]);
            o[i][0] = fmaf(p[i].w, v[3].x, o[i][0]); o[i][1] = fmaf(p[i].w, v[3].y, o[i][1]);
            o[i][2] = fmaf(p[i].w, v[3].z, o[i][2]); o[i][3] = fmaf(p[i].w, v[3].w, o[i][3]);
        }
    }

    // Epilogue: residual + relu, write head slice
    const float* qry = query + (size_t)b * FF * (HH * HD) + h * HD;
    float*       ob  = out   + (size_t)b * FF * (HH * HD) + h * HD;
    #pragma unroll
    for (int i = 0; i < 4; i++) {
        int f = q0 + i;
        float4 qv = *reinterpret_cast<const float4*>(qry + (size_t)f * (HH * HD) + tx * 4);
        float4 r;
        r.x = fmaxf(o[i][0] + qv.x, 0.f);
        r.y = fmaxf(o[i][1] + qv.y, 0.f);
        r.z = fmaxf(o[i][2] + qv.z, 0.f);
        r.w = fmaxf(o[i][3] + qv.w, 0.f);
        *reinterpret_cast<float4*>(ob + (size_t)f * (HH * HD) + tx * 4) = r;
    }
}

// ---------------------------------------------------------------------------
extern "C" void kernel_launch(void* const* d_in, const int* in_sizes, int n_in,
                              void* d_out, int out_size)
{
    const float* query = (const float*)d_in[0];
    const float* key   = (const float*)d_in[1];
    const float* value = (const float*)d_in[2];
    const float* Wq    = (const float*)d_in[3];
    const float* bq    = (const float*)d_in[4];
    const float* Wk    = (const float*)d_in[5];
    const float* bk    = (const float*)d_in[6];
    const float* Wv    = (const float*)d_in[7];
    const float* bv    = (const float*)d_in[8];
    // d_in[9] (Wk2), d_in[10] (bk2) intentionally unused: the unary term is a
    // softmax over a size-1 axis == 1.0 everywhere, independent of K2.
    float* out = (float*)d_out;

    // Projections: Qc, Kc (centered) and V into scratch.
    dim3 g1(4, BB, 3);
    proj_kernel<<<g1, 128>>>(query, key, value, Wq, Wk, Wv, bq, bk, bv);

    // Attention + epilogue. 3 padded 64x68 fp32 tiles of dynamic smem.
    const int smem_bytes = 3 * 64 * 68 * (int)sizeof(float);  // 52224
    cudaFuncSetAttribute(attn_kernel, cudaFuncAttributeMaxDynamicSharedMemorySize, smem_bytes);
    attn_kernel<<<BB * HH, 256, smem_bytes>>>(query, out);
}

// round 5
// speedup vs baseline: 2.2191x; 2.2191x over previous
#include <cuda_runtime.h>
#include <cuda_fp16.h>
#include <math.h>
#include <stdint.h>

#define BB 2048
#define FF 64
#define DD 512
#define AA 512
#define HH 8
#define HD 64

// Scratch (allocation-free rule: __device__ globals). Layout [b, h, f, d].
__device__ float g_Qc[(size_t)BB * HH * FF * HD];
__device__ float g_Kc[(size_t)BB * HH * FF * HD];
__device__ float g_V [(size_t)BB * HH * FF * HD];
// Exact sum-of-V path
__device__ float g_srow[(size_t)BB * DD];   // sum over f of value
__device__ float g_SV  [(size_t)BB * AA];   // srow @ Wv + 64*bv  (fp32 exact)
// Prepacked weights in mma B-fragment order, fp16 hi/lo:
// [p][nt(4)][chunk(8)] blobs of 32KB; blob = [pass(2)][kstep(4)][nb(16)][lane(32)][reg(2)] u32
__device__ uint32_t g_Wt[(size_t)3 * 4 * 8 * 8192];

// ---------------------------------------------------------------------------
// PTX helpers (baseline ISA only — no tcgen05)
// ---------------------------------------------------------------------------
__device__ __forceinline__ uint32_t smem_u32(const void* p) {
    uint32_t a;
    asm("{ .reg .u64 t; cvta.to.shared.u64 t, %1; cvt.u32.u64 %0, t; }" : "=r"(a) : "l"(p));
    return a;
}
__device__ __forceinline__ void ldsm4(uint32_t* r, uint32_t addr) {
    asm volatile("ldmatrix.sync.aligned.m8n8.x4.shared.b16 {%0,%1,%2,%3}, [%4];"
                 : "=r"(r[0]), "=r"(r[1]), "=r"(r[2]), "=r"(r[3]) : "r"(addr));
}
__device__ __forceinline__ void mma16816(float* c, const uint32_t* a, const uint32_t* b) {
    asm volatile(
        "mma.sync.aligned.m16n8k16.row.col.f32.f16.f16.f32 "
        "{%0,%1,%2,%3}, {%4,%5,%6,%7}, {%8,%9}, {%0,%1,%2,%3};"
        : "+f"(c[0]), "+f"(c[1]), "+f"(c[2]), "+f"(c[3])
        : "r"(a[0]), "r"(a[1]), "r"(a[2]), "r"(a[3]), "r"(b[0]), "r"(b[1]));
}
__device__ __forceinline__ void cpasync16(uint32_t dst, const void* src) {
    asm volatile("cp.async.cg.shared.global [%0], [%1], 16;" :: "r"(dst), "l"(src));
}
__device__ __forceinline__ void cp_commit() { asm volatile("cp.async.commit_group;"); }
__device__ __forceinline__ void cp_wait0()  { asm volatile("cp.async.wait_group 0;" ::: "memory"); }

__device__ __forceinline__ uint32_t pack_h2(float a, float b) {
    return (uint32_t)__half_as_ushort(__float2half_rn(a)) |
           ((uint32_t)__half_as_ushort(__float2half_rn(b)) << 16);
}

// ---------------------------------------------------------------------------
// Prepack: W fp32 -> fp16 (hi, lo) directly in mma B-fragment order.
// grid (8 chunks, 4 ntiles, 3 proj), 256 threads.
// ---------------------------------------------------------------------------
__global__ __launch_bounds__(256) void prepack_kernel(
    const float* __restrict__ Wq, const float* __restrict__ Wk, const float* __restrict__ Wv)
{
    const int c  = blockIdx.x;
    const int nt = blockIdx.y;
    const int p  = blockIdx.z;
    const float* W = (p == 0) ? Wq : (p == 1) ? Wk : Wv;
    uint32_t* dst = g_Wt + (((size_t)p * 4 + nt) * 8 + c) * 8192;

    for (int j = 0; j < 32; j++) {
        int s = threadIdx.x + j * 256;            // 0..8191
        int reg  = s & 1;
        int lane = (s >> 1) & 31;
        int nb   = (s >> 6) & 15;
        int ks   = (s >> 10) & 3;
        int pass = s >> 12;
        int k = c * 64 + ks * 16 + 2 * (lane & 3) + 8 * reg;
        int n = nt * 128 + nb * 8 + (lane >> 2);
        float w0 = W[(size_t)k * AA + n];
        float w1 = W[(size_t)(k + 1) * AA + n];
        float v0, v1;
        if (pass == 0) {
            v0 = __half2float(__float2half_rn(w0));
            v1 = __half2float(__float2half_rn(w1));
        } else {
            v0 = w0 - __half2float(__float2half_rn(w0));
            v1 = w1 - __half2float(__float2half_rn(w1));
        }
        dst[s] = pack_h2(v0, v1);
    }
}

// ---------------------------------------------------------------------------
// srow[b][d] = sum_f value[b][f][d]   (fp32 exact)
// ---------------------------------------------------------------------------
__global__ __launch_bounds__(128) void srow_kernel(const float* __restrict__ value)
{
    const int b = blockIdx.x;
    const int t = threadIdx.x;
    const float* src = value + (size_t)b * FF * DD + t * 4;
    float4 s = make_float4(0.f, 0.f, 0.f, 0.f);
    #pragma unroll 8
    for (int f = 0; f < FF; f++) {
        float4 v = *reinterpret_cast<const float4*>(src + (size_t)f * DD);
        s.x += v.x; s.y += v.y; s.z += v.z; s.w += v.w;
    }
    *reinterpret_cast<float4*>(g_srow + (size_t)b * DD + t * 4) = s;
}

// ---------------------------------------------------------------------------
// SV[b][n] = srow[b] . Wv[:,n] + 64*bv[n]   (fp32 exact, tiny GEMM)
// grid (32 mtiles of 64 batches, 8 ntiles of 64), 256 threads, 4x4 micro.
// ---------------------------------------------------------------------------
__global__ __launch_bounds__(256) void sv_kernel(
    const float* __restrict__ Wv, const float* __restrict__ bv)
{
    const int mt = blockIdx.x;
    const int nt = blockIdx.y;
    __shared__ float As[16][68];
    __shared__ float Bs[16][64];
    const int tid = threadIdx.x;
    const int tx = tid & 15, ty = tid >> 4;

    float acc[4][4];
    #pragma unroll
    for (int i = 0; i < 4; i++)
        #pragma unroll
        for (int j = 0; j < 4; j++) acc[i][j] = 0.f;

    for (int k0 = 0; k0 < DD; k0 += 16) {
        #pragma unroll
        for (int j = 0; j < 4; j++) {
            int e = tid + j * 256;
            int m = e >> 4, kk = e & 15;
            As[kk][m] = g_srow[(size_t)(mt * 64 + m) * DD + k0 + kk];
        }
        #pragma unroll
        for (int j = 0; j < 4; j++) {
            int e = tid + j * 256;
            int kk = e >> 6, n = e & 63;
            Bs[kk][n] = Wv[(size_t)(k0 + kk) * AA + nt * 64 + n];
        }
        __syncthreads();
        #pragma unroll
        for (int kk = 0; kk < 16; kk++) {
            float a[4], b[4];
            #pragma unroll
            for (int i = 0; i < 4; i++) a[i] = As[kk][ty * 4 + i];
            #pragma unroll
            for (int j = 0; j < 4; j++) b[j] = Bs[kk][tx * 4 + j];
            #pragma unroll
            for (int i = 0; i < 4; i++)
                #pragma unroll
                for (int j = 0; j < 4; j++)
                    acc[i][j] = fmaf(a[i], b[j], acc[i][j]);
        }
        __syncthreads();
    }
    #pragma unroll
    for (int i = 0; i < 4; i++)
        #pragma unroll
        for (int j = 0; j < 4; j++) {
            int n = nt * 64 + tx * 4 + j;
            g_SV[(size_t)(mt * 64 + ty * 4 + i) * AA + n] = acc[i][j] + 64.f * bv[n];
        }
}

// ---------------------------------------------------------------------------
// Projection GEMM on the tensor pipe (mma.sync fp16, 2-pass weight split).
// grid (1024 mtiles of 128 rows, 4 ntiles of 128, 3 proj), 256 thr (8 warps).
// Warp tile 32(m) x 64(n). Double-buffered: X staged via regs (fp32->fp16),
// W via cp.async of prepacked fragment blobs. Epilogue: mean-centering (Q,K)
// or +bv (V), store to [b,h,f,d].
// SMEM map (dynamic, 103424 B):
//   [0, 36864)       Xs: 2 bufs x 128 rows x 72 fp16 (144 B rows)
//   [36864, 102400)  Bs: 2 bufs x 32 KB fragment blobs
//   epilogue reuse:  [0, 67584) fp32 tile 128 x 132 ; [102400,103424) s_add
// ---------------------------------------------------------------------------
__global__ __launch_bounds__(256, 2) void proj_mma_kernel(
    const float* __restrict__ Xq, const float* __restrict__ Xk, const float* __restrict__ Xv,
    const float* __restrict__ bv)
{
    const int mt = blockIdx.x;
    const int nt = blockIdx.y;
    const int p  = blockIdx.z;
    const float* X   = (p == 0) ? Xq : (p == 1) ? Xk : Xv;
    float*       dst = (p == 0) ? g_Qc : (p == 1) ? g_Kc : g_V;

    extern __shared__ __align__(16) unsigned char smd[];
    const uint32_t sbase = smem_u32(smd);
    const int tid   = threadIdx.x;
    const int lane  = tid & 31;
    const int wid   = tid >> 5;
    const int warpM = wid >> 1;      // 0..3
    const int warpN = wid & 1;       // 0..1

    const float* Xb = X + (size_t)mt * 128 * DD;
    const uint32_t* Wg = g_Wt + (((size_t)p * 4 + nt) * 8) * 8192;

    float acc[2][8][4];
    #pragma unroll
    for (int mf = 0; mf < 2; mf++)
        #pragma unroll
        for (int nb = 0; nb < 8; nb++)
            #pragma unroll
            for (int r = 0; r < 4; r++) acc[mf][nb][r] = 0.f;

    uint2 xr[8];
    // per-thread X tile coords: idx = tid + i*256 -> m = idx>>4, kq = idx&15
    #define LOADX(c) do { \
        _Pragma("unroll") \
        for (int i = 0; i < 8; i++) { \
            int idx = tid + i * 256; \
            int m = idx >> 4, kq = idx & 15; \
            float4 v = *reinterpret_cast<const float4*>(Xb + (size_t)m * DD + (c) * 64 + kq * 4); \
            xr[i].x = pack_h2(v.x, v.y); \
            xr[i].y = pack_h2(v.z, v.w); \
        } } while (0)
    #define STOREX(buf) do { \
        _Pragma("unroll") \
        for (int i = 0; i < 8; i++) { \
            int idx = tid + i * 256; \
            int m = idx >> 4, kq = idx & 15; \
            *reinterpret_cast<uint2*>(smd + (buf) * 18432 + m * 144 + kq * 8) = xr[i]; \
        } } while (0)
    #define CPB(c, buf) do { \
        const char* src = reinterpret_cast<const char*>(Wg + (size_t)(c) * 8192); \
        _Pragma("unroll") \
        for (int i = 0; i < 8; i++) { \
            int off = (tid + i * 256) * 16; \
            cpasync16(sbase + 36864 + (buf) * 32768 + off, src + off); \
        } \
        cp_commit(); } while (0)

    LOADX(0);
    CPB(0, 0);

    for (int c = 0; c < 8; ++c) {
        const int buf = c & 1;
        STOREX(buf);
        cp_wait0();
        __syncthreads();
        if (c < 7) { CPB(c + 1, buf ^ 1); LOADX(c + 1); }

        // compute over chunk c
        const uint32_t abase = sbase + buf * 18432;
        #pragma unroll
        for (int ks = 0; ks < 4; ks++) {
            uint32_t a0[4], a1[4];
            uint32_t ad = abase + (warpM * 32 + (lane & 15)) * 144 + ks * 32 + (lane >> 4) * 16;
            ldsm4(a0, ad);
            ldsm4(a1, ad + 16 * 144);
            #pragma unroll
            for (int pass = 0; pass < 2; pass++) {
                #pragma unroll
                for (int nb = 0; nb < 8; nb++) {
                    uint2 bb = *reinterpret_cast<const uint2*>(
                        smd + 36864 + buf * 32768 +
                        ((((pass * 4 + ks) * 16) + warpN * 8 + nb) * 32 + lane) * 8);
                    mma16816(acc[0][nb], a0, &bb.x);
                    mma16816(acc[1][nb], a1, &bb.x);
                }
            }
        }
        __syncthreads();
    }

    // ---- epilogue ----
    float* tile  = reinterpret_cast<float*>(smd);           // 128 x 132
    float* s_add = reinterpret_cast<float*>(smd + 102400);  // [2][128]
    #pragma unroll
    for (int mf = 0; mf < 2; mf++) {
        #pragma unroll
        for (int nb = 0; nb < 8; nb++) {
            int row = warpM * 32 + mf * 16 + (lane >> 2);
            int col = warpN * 64 + nb * 8 + 2 * (lane & 3);
            *reinterpret_cast<float2*>(&tile[row * 132 + col]) =
                make_float2(acc[mf][nb][0], acc[mf][nb][1]);
            *reinterpret_cast<float2*>(&tile[(row + 8) * 132 + col]) =
                make_float2(acc[mf][nb][2], acc[mf][nb][3]);
        }
    }
    __syncthreads();

    {
        int col = tid & 127;
        int g   = tid >> 7;
        if (p < 2) {
            float s = 0.f;
            #pragma unroll 8
            for (int r = 0; r < 64; r++) s += tile[(g * 64 + r) * 132 + col];
            s_add[g * 128 + col] = -s * (1.f / 64.f);
        } else {
            s_add[g * 128 + col] = bv[nt * 128 + col];
        }
    }
    __syncthreads();

    #pragma unroll 4
    for (int i = 0; i < 16; i++) {
        int id = tid + i * 256;          // 0..4095
        int r  = id >> 5;                // 0..127
        int cq = id & 31;                // float4 group 0..31
        float4 v = *reinterpret_cast<const float4*>(&tile[r * 132 + cq * 4]);
        const float* ad = &s_add[(r >> 6) * 128 + cq * 4];
        v.x += ad[0]; v.y += ad[1]; v.z += ad[2]; v.w += ad[3];
        int n0 = nt * 128 + cq * 4;
        int h  = n0 >> 6;
        int d0 = n0 & 63;
        int batch = mt * 2 + (r >> 6);
        int f     = r & 63;
        *reinterpret_cast<float4*>(dst + (((size_t)batch * HH + h) * FF + f) * HD + d0) = v;
    }
}

// ---------------------------------------------------------------------------
// Attention per (b,h): S = Qc Kc^T, P = softmax(S) (NO +1 — the exact
// sum-of-V term g_SV is added in the epilogue), O = P V + SV + query, relu.
// ---------------------------------------------------------------------------
__global__ __launch_bounds__(256) void attn_kernel(
    const float* __restrict__ query, float* __restrict__ out)
{
    const int bh = blockIdx.x;
    const int b  = bh >> 3;
    const int h  = bh & 7;

    extern __shared__ float sm[];
    float* Qs = sm;
    float* Ks = sm + 64 * 68;
    float* Ss = sm + 2 * 64 * 68;

    const int tid = threadIdx.x;
    const int tx  = tid & 15;
    const int ty  = tid >> 4;
    const int q0  = ty * 4;
    const int k0  = tx * 4;

    const float* Qg = g_Qc + (size_t)bh * FF * HD;
    const float* Kg = g_Kc + (size_t)bh * FF * HD;
    const float* Vg = g_V  + (size_t)bh * FF * HD;

    #pragma unroll
    for (int i = 0; i < 4; i++) {
        int idx = tid + i * 256;
        int f   = idx >> 4;
        int dv  = idx & 15;
        *reinterpret_cast<float4*>(Qs + f * 68 + dv * 4) =
            *reinterpret_cast<const float4*>(Qg + f * 64 + dv * 4);
        *reinterpret_cast<float4*>(Ks + f * 68 + dv * 4) =
            *reinterpret_cast<const float4*>(Kg + f * 64 + dv * 4);
    }
    __syncthreads();

    float s[4][4];
    #pragma unroll
    for (int i = 0; i < 4; i++)
        #pragma unroll
        for (int j = 0; j < 4; j++) s[i][j] = 0.f;

    for (int d = 0; d < 64; d += 4) {
        float4 a[4], c[4];
        #pragma unroll
        for (int i = 0; i < 4; i++) a[i] = *reinterpret_cast<const float4*>(Qs + (q0 + i) * 68 + d);
        #pragma unroll
        for (int j = 0; j < 4; j++) c[j] = *reinterpret_cast<const float4*>(Ks + (k0 + j) * 68 + d);
        #pragma unroll
        for (int i = 0; i < 4; i++) {
            #pragma unroll
            for (int j = 0; j < 4; j++) {
                s[i][j] = fmaf(a[i].x, c[j].x, s[i][j]);
                s[i][j] = fmaf(a[i].y, c[j].y, s[i][j]);
                s[i][j] = fmaf(a[i].z, c[j].z, s[i][j]);
                s[i][j] = fmaf(a[i].w, c[j].w, s[i][j]);
            }
        }
    }
    #pragma unroll
    for (int i = 0; i < 4; i++)
        #pragma unroll
        for (int j = 0; j < 4; j++)
            Ss[(q0 + i) * 68 + (k0 + j)] = s[i][j];
    __syncthreads();

    #pragma unroll
    for (int i = 0; i < 4; i++) {
        int idx = tid + i * 256;
        int f   = idx >> 4;
        int dv  = idx & 15;
        *reinterpret_cast<float4*>(Qs + f * 68 + dv * 4) =
            *reinterpret_cast<const float4*>(Vg + f * 64 + dv * 4);
    }

    {
        int q    = tid >> 2;
        int part = tid & 3;
        float* row = Ss + q * 68 + part * 16;
        float mx = -INFINITY;
        #pragma unroll
        for (int j = 0; j < 16; j++) mx = fmaxf(mx, row[j]);
        mx = fmaxf(mx, __shfl_xor_sync(0xFFFFFFFFu, mx, 1));
        mx = fmaxf(mx, __shfl_xor_sync(0xFFFFFFFFu, mx, 2));
        float e[16];
        float sum = 0.f;
        #pragma unroll
        for (int j = 0; j < 16; j++) { e[j] = expf(row[j] - mx); sum += e[j]; }
        sum += __shfl_xor_sync(0xFFFFFFFFu, sum, 1);
        sum += __shfl_xor_sync(0xFFFFFFFFu, sum, 2);
        float inv = 1.f / sum;
        #pragma unroll
        for (int j = 0; j < 16; j++) row[j] = e[j] * inv;   // no +1: SV added exactly below
    }
    __syncthreads();

    float o[4][4];
    #pragma unroll
    for (int i = 0; i < 4; i++)
        #pragma unroll
        for (int j = 0; j < 4; j++) o[i][j] = 0.f;

    float* Vs = Qs;
    for (int k = 0; k < 64; k += 4) {
        float4 pr[4], v[4];
        #pragma unroll
        for (int i = 0; i < 4; i++) pr[i] = *reinterpret_cast<const float4*>(Ss + (q0 + i) * 68 + k);
        #pragma unroll
        for (int kk = 0; kk < 4; kk++) v[kk] = *reinterpret_cast<const float4*>(Vs + (k + kk) * 68 + tx * 4);
        #pragma unroll
        for (int i = 0; i < 4; i++) {
            o[i][0] = fmaf(pr[i].x, v[0].x, o[i][0]); o[i][1] = fmaf(pr[i].x, v[0].y, o[i][1]);
            o[i][2] = fmaf(pr[i].x, v[0].z, o[i][2]); o[i][3] = fmaf(pr[i].x, v[0].w, o[i][3]);
            o[i][0] = fmaf(pr[i].y, v[1].x, o[i][0]); o[i][1] = fmaf(pr[i].y, v[1].y, o[i][1]);
            o[i][2] = fmaf(pr[i].y, v[1].z, o[i][2]); o[i][3] = fmaf(pr[i].y, v[1].w, o[i][3]);
            o[i][0] = fmaf(pr[i].z, v[2].x, o[i][0]); o[i][1] = fmaf(pr[i].z, v[2].y, o[i][1]);
            o[i][2] = fmaf(pr[i].z, v[2].z, o[i][2]); o[i][3] = fmaf(pr[i].z, v[2].w, o[i][3]);
            o[i][0] = fmaf(pr[i].w, v[3].x, o[i][0]); o[i][1] = fmaf(pr[i].w, v[3].y, o[i][1]);
            o[i][2] = fmaf(pr[i].w, v[3].z, o[i][2]); o[i][3] = fmaf(pr[i].w, v[3].w, o[i][3]);
        }
    }

    const float* qry = query + (size_t)b * FF * (HH * HD) + h * HD;
    float*       ob  = out   + (size_t)b * FF * (HH * HD) + h * HD;
    float4 sv4 = *reinterpret_cast<const float4*>(g_SV + (size_t)b * AA + h * HD + tx * 4);
    #pragma unroll
    for (int i = 0; i < 4; i++) {
        int f = q0 + i;
        float4 qv = *reinterpret_cast<const float4*>(qry + (size_t)f * (HH * HD) + tx * 4);
        float4 r;
        r.x = fmaxf(o[i][0] + sv4.x + qv.x, 0.f);
        r.y = fmaxf(o[i][1] + sv4.y + qv.y, 0.f);
        r.z = fmaxf(o[i][2] + sv4.z + qv.z, 0.f);
        r.w = fmaxf(o[i][3] + sv4.w + qv.w, 0.f);
        *reinterpret_cast<float4*>(ob + (size_t)f * (HH * HD) + tx * 4) = r;
    }
}

// ---------------------------------------------------------------------------
extern "C" void kernel_launch(void* const* d_in, const int* in_sizes, int n_in,
                              void* d_out, int out_size)
{
    const float* query = (const float*)d_in[0];
    const float* key   = (const float*)d_in[1];
    const float* value = (const float*)d_in[2];
    const float* Wq    = (const float*)d_in[3];
    // d_in[4] (bq), d_in[6] (bk): cancel exactly under mean-centering.
    const float* Wk    = (const float*)d_in[5];
    const float* Wv    = (const float*)d_in[7];
    const float* bv    = (const float*)d_in[8];
    // d_in[9]/d_in[10] (Wk2/bk2) unused: unary softmax over size-1 axis == 1.
    float* out = (float*)d_out;

    prepack_kernel<<<dim3(8, 4, 3), 256>>>(Wq, Wk, Wv);
    srow_kernel<<<BB, 128>>>(value);
    sv_kernel<<<dim3(32, 8), 256>>>(Wv, bv);

    const int proj_smem = 103424;
    cudaFuncSetAttribute(proj_mma_kernel, cudaFuncAttributeMaxDynamicSharedMemorySize, proj_smem);
    proj_mma_kernel<<<dim3(1024, 4, 3), 256, proj_smem>>>(query, key, value, bv);

    const int attn_smem = 3 * 64 * 68 * (int)sizeof(float);
    cudaFuncSetAttribute(attn_kernel, cudaFuncAttributeMaxDynamicSharedMemorySize, attn_smem);
    attn_kernel<<<BB * HH, 256, attn_smem>>>(query, out);
}

// round 6
// speedup vs baseline: 3.0375x; 1.3688x over previous
#include <cuda_runtime.h>
#include <cuda_fp16.h>
#include <math.h>
#include <stdint.h>

#define BB 2048
#define FF 64
#define DD 512
#define AA 512
#define HH 8
#define HD 64

// Scratch (allocation-free rule: __device__ globals). Layout [b, h, f, d].
__device__ float g_Qc[(size_t)BB * HH * FF * HD];
__device__ float g_Kc[(size_t)BB * HH * FF * HD];
__device__ float g_V [(size_t)BB * HH * FF * HD];
// Exact sum-of-V path
__device__ float g_srow[(size_t)BB * DD];   // sum over f of value
__device__ float g_SV  [(size_t)BB * AA];   // srow @ Wv + 64*bv  (fp32 exact)
// Prepacked weights in mma B-fragment order, fp16 (single pass, hi only):
// [p][nt(4)][chunk(8)] blobs of 16KB; blob = [kstep(4)][nb(16)][lane(32)][reg(2)] u32
__device__ uint32_t g_Wt[(size_t)3 * 4 * 8 * 4096];

// ---------------------------------------------------------------------------
// PTX helpers (baseline ISA only — no tcgen05)
// ---------------------------------------------------------------------------
__device__ __forceinline__ uint32_t smem_u32(const void* p) {
    uint32_t a;
    asm("{ .reg .u64 t; cvta.to.shared.u64 t, %1; cvt.u32.u64 %0, t; }" : "=r"(a) : "l"(p));
    return a;
}
__device__ __forceinline__ void ldsm4(uint32_t* r, uint32_t addr) {
    asm volatile("ldmatrix.sync.aligned.m8n8.x4.shared.b16 {%0,%1,%2,%3}, [%4];"
                 : "=r"(r[0]), "=r"(r[1]), "=r"(r[2]), "=r"(r[3]) : "r"(addr));
}
__device__ __forceinline__ void mma16816(float* c, const uint32_t* a, const uint32_t* b) {
    asm volatile(
        "mma.sync.aligned.m16n8k16.row.col.f32.f16.f16.f32 "
        "{%0,%1,%2,%3}, {%4,%5,%6,%7}, {%8,%9}, {%0,%1,%2,%3};"
        : "+f"(c[0]), "+f"(c[1]), "+f"(c[2]), "+f"(c[3])
        : "r"(a[0]), "r"(a[1]), "r"(a[2]), "r"(a[3]), "r"(b[0]), "r"(b[1]));
}
__device__ __forceinline__ void cpasync16(uint32_t dst, const void* src) {
    asm volatile("cp.async.cg.shared.global [%0], [%1], 16;" :: "r"(dst), "l"(src));
}
__device__ __forceinline__ void cp_commit() { asm volatile("cp.async.commit_group;"); }
__device__ __forceinline__ void cp_wait0()  { asm volatile("cp.async.wait_group 0;" ::: "memory"); }

__device__ __forceinline__ uint32_t pack_h2(float a, float b) {
    return (uint32_t)__half_as_ushort(__float2half_rn(a)) |
           ((uint32_t)__half_as_ushort(__float2half_rn(b)) << 16);
}

// ---------------------------------------------------------------------------
// Prepack: W fp32 -> fp16 directly in mma B-fragment order (single pass).
// grid (8 chunks, 4 ntiles, 3 proj), 256 threads.
// ---------------------------------------------------------------------------
__global__ __launch_bounds__(256) void prepack_kernel(
    const float* __restrict__ Wq, const float* __restrict__ Wk, const float* __restrict__ Wv)
{
    const int c  = blockIdx.x;
    const int nt = blockIdx.y;
    const int p  = blockIdx.z;
    const float* W = (p == 0) ? Wq : (p == 1) ? Wk : Wv;
    uint32_t* dst = g_Wt + (((size_t)p * 4 + nt) * 8 + c) * 4096;

    for (int j = 0; j < 16; j++) {
        int s = threadIdx.x + j * 256;            // 0..4095
        int reg  = s & 1;
        int lane = (s >> 1) & 31;
        int nb   = (s >> 6) & 15;
        int ks   = s >> 10;                       // 0..3
        int k = c * 64 + ks * 16 + 2 * (lane & 3) + 8 * reg;
        int n = nt * 128 + nb * 8 + (lane >> 2);
        float w0 = W[(size_t)k * AA + n];
        float w1 = W[(size_t)(k + 1) * AA + n];
        dst[s] = pack_h2(w0, w1);
    }
}

// ---------------------------------------------------------------------------
// srow[b][d] = sum_f value[b][f][d]   (fp32 exact)
// ---------------------------------------------------------------------------
__global__ __launch_bounds__(128) void srow_kernel(const float* __restrict__ value)
{
    const int b = blockIdx.x;
    const int t = threadIdx.x;
    const float* src = value + (size_t)b * FF * DD + t * 4;
    float4 s = make_float4(0.f, 0.f, 0.f, 0.f);
    #pragma unroll 8
    for (int f = 0; f < FF; f++) {
        float4 v = *reinterpret_cast<const float4*>(src + (size_t)f * DD);
        s.x += v.x; s.y += v.y; s.z += v.z; s.w += v.w;
    }
    *reinterpret_cast<float4*>(g_srow + (size_t)b * DD + t * 4) = s;
}

// ---------------------------------------------------------------------------
// SV[b][n] = srow[b] . Wv[:,n] + 64*bv[n]   (fp32 exact, tiny GEMM)
// ---------------------------------------------------------------------------
__global__ __launch_bounds__(256) void sv_kernel(
    const float* __restrict__ Wv, const float* __restrict__ bv)
{
    const int mt = blockIdx.x;
    const int nt = blockIdx.y;
    __shared__ float As[16][68];
    __shared__ float Bs[16][64];
    const int tid = threadIdx.x;
    const int tx = tid & 15, ty = tid >> 4;

    float acc[4][4];
    #pragma unroll
    for (int i = 0; i < 4; i++)
        #pragma unroll
        for (int j = 0; j < 4; j++) acc[i][j] = 0.f;

    for (int k0 = 0; k0 < DD; k0 += 16) {
        #pragma unroll
        for (int j = 0; j < 4; j++) {
            int e = tid + j * 256;
            int m = e >> 4, kk = e & 15;
            As[kk][m] = g_srow[(size_t)(mt * 64 + m) * DD + k0 + kk];
        }
        #pragma unroll
        for (int j = 0; j < 4; j++) {
            int e = tid + j * 256;
            int kk = e >> 6, n = e & 63;
            Bs[kk][n] = Wv[(size_t)(k0 + kk) * AA + nt * 64 + n];
        }
        __syncthreads();
        #pragma unroll
        for (int kk = 0; kk < 16; kk++) {
            float a[4], b[4];
            #pragma unroll
            for (int i = 0; i < 4; i++) a[i] = As[kk][ty * 4 + i];
            #pragma unroll
            for (int j = 0; j < 4; j++) b[j] = Bs[kk][tx * 4 + j];
            #pragma unroll
            for (int i = 0; i < 4; i++)
                #pragma unroll
                for (int j = 0; j < 4; j++)
                    acc[i][j] = fmaf(a[i], b[j], acc[i][j]);
        }
        __syncthreads();
    }
    #pragma unroll
    for (int i = 0; i < 4; i++)
        #pragma unroll
        for (int j = 0; j < 4; j++) {
            int n = nt * 64 + tx * 4 + j;
            g_SV[(size_t)(mt * 64 + ty * 4 + i) * AA + n] = acc[i][j] + 64.f * bv[n];
        }
}

// ---------------------------------------------------------------------------
// Projection GEMM (mma.sync fp16, single pass). grid (4 nt, 1024 mt, 3 p):
// nt fastest so the 4 CTAs sharing one X tile run in the same wave (L2 reuse).
// Per CTA: 128(M) x 128(N) x 512(K), 8 warps, warp tile 32x64.
// SMEM (dynamic, 69632 B): Xs 2 x 18432 | Bs 2 x 16384.
// Epilogue reuse: fp32 tile 128 x 132 at [0, 67584), s_add at [67584, 68608).
// ---------------------------------------------------------------------------
__global__ __launch_bounds__(256, 2) void proj_mma_kernel(
    const float* __restrict__ Xq, const float* __restrict__ Xk, const float* __restrict__ Xv,
    const float* __restrict__ bv)
{
    const int nt = blockIdx.x;
    const int mt = blockIdx.y;
    const int p  = blockIdx.z;
    const float* X   = (p == 0) ? Xq : (p == 1) ? Xk : Xv;
    float*       dst = (p == 0) ? g_Qc : (p == 1) ? g_Kc : g_V;

    extern __shared__ __align__(16) unsigned char smd[];
    const uint32_t sbase = smem_u32(smd);
    const int tid   = threadIdx.x;
    const int lane  = tid & 31;
    const int wid   = tid >> 5;
    const int warpM = wid >> 1;      // 0..3
    const int warpN = wid & 1;       // 0..1

    const float* Xb = X + (size_t)mt * 128 * DD;
    const uint32_t* Wg = g_Wt + (((size_t)p * 4 + nt) * 8) * 4096;

    float acc[2][8][4];
    #pragma unroll
    for (int mf = 0; mf < 2; mf++)
        #pragma unroll
        for (int nb = 0; nb < 8; nb++)
            #pragma unroll
            for (int r = 0; r < 4; r++) acc[mf][nb][r] = 0.f;

    uint2 xr[8];
    #define LOADX(c) do { \
        _Pragma("unroll") \
        for (int i = 0; i < 8; i++) { \
            int idx = tid + i * 256; \
            int m = idx >> 4, kq = idx & 15; \
            float4 v = *reinterpret_cast<const float4*>(Xb + (size_t)m * DD + (c) * 64 + kq * 4); \
            xr[i].x = pack_h2(v.x, v.y); \
            xr[i].y = pack_h2(v.z, v.w); \
        } } while (0)
    #define STOREX(buf) do { \
        _Pragma("unroll") \
        for (int i = 0; i < 8; i++) { \
            int idx = tid + i * 256; \
            int m = idx >> 4, kq = idx & 15; \
            *reinterpret_cast<uint2*>(smd + (buf) * 18432 + m * 144 + kq * 8) = xr[i]; \
        } } while (0)
    #define CPB(c, buf) do { \
        const char* src = reinterpret_cast<const char*>(Wg + (size_t)(c) * 4096); \
        _Pragma("unroll") \
        for (int i = 0; i < 4; i++) { \
            int off = (tid + i * 256) * 16; \
            cpasync16(sbase + 36864 + (buf) * 16384 + off, src + off); \
        } \
        cp_commit(); } while (0)

    LOADX(0);
    CPB(0, 0);

    for (int c = 0; c < 8; ++c) {
        const int buf = c & 1;
        STOREX(buf);
        cp_wait0();
        __syncthreads();
        if (c < 7) { CPB(c + 1, buf ^ 1); LOADX(c + 1); }

        const uint32_t abase = sbase + buf * 18432;
        #pragma unroll
        for (int ks = 0; ks < 4; ks++) {
            uint32_t a0[4], a1[4];
            uint32_t ad = abase + (warpM * 32 + (lane & 15)) * 144 + ks * 32 + (lane >> 4) * 16;
            ldsm4(a0, ad);
            ldsm4(a1, ad + 16 * 144);
            #pragma unroll
            for (int nb = 0; nb < 8; nb++) {
                uint2 bb = *reinterpret_cast<const uint2*>(
                    smd + 36864 + buf * 16384 +
                    (((ks * 16) + warpN * 8 + nb) * 32 + lane) * 8);
                mma16816(acc[0][nb], a0, &bb.x);
                mma16816(acc[1][nb], a1, &bb.x);
            }
        }
        __syncthreads();
    }

    // ---- epilogue ----
    float* tile  = reinterpret_cast<float*>(smd);          // 128 x 132
    float* s_add = reinterpret_cast<float*>(smd + 67584);  // [2][128]
    #pragma unroll
    for (int mf = 0; mf < 2; mf++) {
        #pragma unroll
        for (int nb = 0; nb < 8; nb++) {
            int row = warpM * 32 + mf * 16 + (lane >> 2);
            int col = warpN * 64 + nb * 8 + 2 * (lane & 3);
            *reinterpret_cast<float2*>(&tile[row * 132 + col]) =
                make_float2(acc[mf][nb][0], acc[mf][nb][1]);
            *reinterpret_cast<float2*>(&tile[(row + 8) * 132 + col]) =
                make_float2(acc[mf][nb][2], acc[mf][nb][3]);
        }
    }
    __syncthreads();

    {
        int col = tid & 127;
        int g   = tid >> 7;
        if (p < 2) {
            float s = 0.f;
            #pragma unroll 8
            for (int r = 0; r < 64; r++) s += tile[(g * 64 + r) * 132 + col];
            s_add[g * 128 + col] = -s * (1.f / 64.f);
        } else {
            s_add[g * 128 + col] = bv[nt * 128 + col];
        }
    }
    __syncthreads();

    #pragma unroll 4
    for (int i = 0; i < 16; i++) {
        int id = tid + i * 256;          // 0..4095
        int r  = id >> 5;                // 0..127
        int cq = id & 31;                // float4 group 0..31
        float4 v = *reinterpret_cast<const float4*>(&tile[r * 132 + cq * 4]);
        const float* ad = &s_add[(r >> 6) * 128 + cq * 4];
        v.x += ad[0]; v.y += ad[1]; v.z += ad[2]; v.w += ad[3];
        int n0 = nt * 128 + cq * 4;
        int h  = n0 >> 6;
        int d0 = n0 & 63;
        int batch = mt * 2 + (r >> 6);
        int f     = r & 63;
        *reinterpret_cast<float4*>(dst + (((size_t)batch * HH + h) * FF + f) * HD + d0) = v;
    }
}

// ---------------------------------------------------------------------------
// Attention per (b,h): S = Qc Kc^T, P = softmax(S) (exact SV added in the
// epilogue instead of +1), O = P V + SV + query, relu.
// 128 threads = 2 heads x 64 threads (8x8 thread grid, 8x8 microtile each).
// Interleaved ownership (row = t + 8*i) -> conflict-free LDS.128 everywhere.
// SMEM per head: Qs(->Vt), Ks, Ss, each 64 x 68 fp32.
// ---------------------------------------------------------------------------
__global__ __launch_bounds__(128) void attn_kernel(
    const float* __restrict__ query, float* __restrict__ out)
{
    const int hs   = threadIdx.x >> 6;        // head select within block
    const int htid = threadIdx.x & 63;
    const int bh = blockIdx.x * 2 + hs;
    const int b  = bh >> 3;
    const int h  = bh & 7;

    extern __shared__ float sm[];
    float* Qs = sm + hs * 3 * 64 * 68;        // later reused as Vt [d][f]
    float* Ks = Qs + 64 * 68;
    float* Ss = Qs + 2 * 64 * 68;

    const int tx = htid & 7;                  // col group
    const int ty = htid >> 3;                 // row group

    const float* Qg = g_Qc + (size_t)bh * FF * HD;
    const float* Kg = g_Kc + (size_t)bh * FF * HD;
    const float* Vg = g_V  + (size_t)bh * FF * HD;

    // Load Qc, Kc (16 float4 per thread per tile). dv fixed per thread.
    {
        const int dv = htid & 15;
        const int f0 = htid >> 4;
        #pragma unroll
        for (int i = 0; i < 16; i++) {
            int f = f0 + i * 4;
            *reinterpret_cast<float4*>(Qs + f * 68 + dv * 4) =
                *reinterpret_cast<const float4*>(Qg + f * 64 + dv * 4);
            *reinterpret_cast<float4*>(Ks + f * 68 + dv * 4) =
                *reinterpret_cast<const float4*>(Kg + f * 64 + dv * 4);
        }
    }
    __syncthreads();

    // S = Qc @ Kc^T, 8x8 per thread, interleaved rows/cols (stride 8)
    float s[8][8];
    #pragma unroll
    for (int i = 0; i < 8; i++)
        #pragma unroll
        for (int j = 0; j < 8; j++) s[i][j] = 0.f;

    #pragma unroll 4
    for (int d = 0; d < 64; d += 4) {
        float4 a[8], c[8];
        #pragma unroll
        for (int i = 0; i < 8; i++) a[i] = *reinterpret_cast<const float4*>(Qs + (ty + 8 * i) * 68 + d);
        #pragma unroll
        for (int j = 0; j < 8; j++) c[j] = *reinterpret_cast<const float4*>(Ks + (tx + 8 * j) * 68 + d);
        #pragma unroll
        for (int i = 0; i < 8; i++)
            #pragma unroll
            for (int j = 0; j < 8; j++) {
                s[i][j] = fmaf(a[i].x, c[j].x, s[i][j]);
                s[i][j] = fmaf(a[i].y, c[j].y, s[i][j]);
                s[i][j] = fmaf(a[i].z, c[j].z, s[i][j]);
                s[i][j] = fmaf(a[i].w, c[j].w, s[i][j]);
            }
    }
    #pragma unroll
    for (int i = 0; i < 8; i++)
        #pragma unroll
        for (int j = 0; j < 8; j++)
            Ss[(ty + 8 * i) * 68 + tx + 8 * j] = s[i][j];
    __syncthreads();

    // Load V transposed into Qs: Vt[d][f]
    {
        const int dv = htid & 15;
        const int f0 = htid >> 4;
        #pragma unroll
        for (int i = 0; i < 16; i++) {
            int f = f0 + i * 4;
            float4 v = *reinterpret_cast<const float4*>(Vg + f * 64 + dv * 4);
            Qs[(dv * 4 + 0) * 68 + f] = v.x;
            Qs[(dv * 4 + 1) * 68 + f] = v.y;
            Qs[(dv * 4 + 2) * 68 + f] = v.z;
            Qs[(dv * 4 + 3) * 68 + f] = v.w;
        }
    }

    // Row softmax (one row per thread), vectorized float4
    {
        float* row = Ss + htid * 68;
        float4 e[16];
        float mx = -INFINITY;
        #pragma unroll
        for (int j = 0; j < 16; j++) {
            e[j] = *reinterpret_cast<const float4*>(row + j * 4);
            mx = fmaxf(mx, fmaxf(fmaxf(e[j].x, e[j].y), fmaxf(e[j].z, e[j].w)));
        }
        float sum = 0.f;
        #pragma unroll
        for (int j = 0; j < 16; j++) {
            e[j].x = __expf(e[j].x - mx); e[j].y = __expf(e[j].y - mx);
            e[j].z = __expf(e[j].z - mx); e[j].w = __expf(e[j].w - mx);
            sum += e[j].x + e[j].y + e[j].z + e[j].w;
        }
        float inv = 1.f / sum;
        #pragma unroll
        for (int j = 0; j < 16; j++) {
            e[j].x *= inv; e[j].y *= inv; e[j].z *= inv; e[j].w *= inv;
            *reinterpret_cast<float4*>(row + j * 4) = e[j];
        }
    }
    __syncthreads();

    // O = P @ V: o[i][j] for rows f = ty+8i, cols d = tx+8j (via Vt rows)
    float o[8][8];
    #pragma unroll
    for (int i = 0; i < 8; i++)
        #pragma unroll
        for (int j = 0; j < 8; j++) o[i][j] = 0.f;

    #pragma unroll 4
    for (int k = 0; k < 64; k += 4) {
        float4 pr[8], v[8];
        #pragma unroll
        for (int i = 0; i < 8; i++) pr[i] = *reinterpret_cast<const float4*>(Ss + (ty + 8 * i) * 68 + k);
        #pragma unroll
        for (int j = 0; j < 8; j++) v[j] = *reinterpret_cast<const float4*>(Qs + (tx + 8 * j) * 68 + k);
        #pragma unroll
        for (int i = 0; i < 8; i++)
            #pragma unroll
            for (int j = 0; j < 8; j++) {
                o[i][j] = fmaf(pr[i].x, v[j].x, o[i][j]);
                o[i][j] = fmaf(pr[i].y, v[j].y, o[i][j]);
                o[i][j] = fmaf(pr[i].z, v[j].z, o[i][j]);
                o[i][j] = fmaf(pr[i].w, v[j].w, o[i][j]);
            }
    }
    __syncthreads();

    // Re-layout O through Ss for vectorized global stores
    #pragma unroll
    for (int i = 0; i < 8; i++)
        #pragma unroll
        for (int j = 0; j < 8; j++)
            Ss[(ty + 8 * i) * 68 + tx + 8 * j] = o[i][j];
    __syncthreads();

    // Epilogue: out = relu(O + SV + query)
    {
        const int dv = htid & 15;
        const int f0 = htid >> 4;
        float4 sv4 = *reinterpret_cast<const float4*>(g_SV + (size_t)b * AA + h * HD + dv * 4);
        const float* qry = query + (size_t)b * FF * (HH * HD) + h * HD + dv * 4;
        float*       ob  = out   + (size_t)b * FF * (HH * HD) + h * HD + dv * 4;
        #pragma unroll
        for (int i = 0; i < 16; i++) {
            int f = f0 + i * 4;
            float4 ov = *reinterpret_cast<const float4*>(Ss + f * 68 + dv * 4);
            float4 qv = *reinterpret_cast<const float4*>(qry + (size_t)f * (HH * HD));
            float4 r;
            r.x = fmaxf(ov.x + sv4.x + qv.x, 0.f);
            r.y = fmaxf(ov.y + sv4.y + qv.y, 0.f);
            r.z = fmaxf(ov.z + sv4.z + qv.z, 0.f);
            r.w = fmaxf(ov.w + sv4.w + qv.w, 0.f);
            *reinterpret_cast<float4*>(ob + (size_t)f * (HH * HD)) = r;
        }
    }
}

// ---------------------------------------------------------------------------
extern "C" void kernel_launch(void* const* d_in, const int* in_sizes, int n_in,
                              void* d_out, int out_size)
{
    const float* query = (const float*)d_in[0];
    const float* key   = (const float*)d_in[1];
    const float* value = (const float*)d_in[2];
    const float* Wq    = (const float*)d_in[3];
    // d_in[4] (bq), d_in[6] (bk): cancel exactly under mean-centering.
    const float* Wk    = (const float*)d_in[5];
    const float* Wv    = (const float*)d_in[7];
    const float* bv    = (const float*)d_in[8];
    // d_in[9]/d_in[10] (Wk2/bk2) unused: unary softmax over size-1 axis == 1.
    float* out = (float*)d_out;

    prepack_kernel<<<dim3(8, 4, 3), 256>>>(Wq, Wk, Wv);
    srow_kernel<<<BB, 128>>>(value);
    sv_kernel<<<dim3(32, 8), 256>>>(Wv, bv);

    const int proj_smem = 69632;
    cudaFuncSetAttribute(proj_mma_kernel, cudaFuncAttributeMaxDynamicSharedMemorySize, proj_smem);
    proj_mma_kernel<<<dim3(4, 1024, 3), 256, proj_smem>>>(query, key, value, bv);

    const int attn_smem = 2 * 3 * 64 * 68 * (int)sizeof(float);  // 104448
    cudaFuncSetAttribute(attn_kernel, cudaFuncAttributeMaxDynamicSharedMemorySize, attn_smem);
    attn_kernel<<<BB * HH / 2, 128, attn_smem>>>(query, out);
}

// round 7
// speedup vs baseline: 3.3100x; 1.0897x over previous
#include <cuda_runtime.h>
#include <cuda_fp16.h>
#include <math.h>
#include <stdint.h>

#define BB 2048
#define FF 64
#define DD 512
#define AA 512
#define HH 8
#define HD 64

// Scratch (allocation-free rule: __device__ globals). Layout [b, h, f, d], fp16.
__device__ __align__(16) __half g_Qh[(size_t)BB * HH * FF * HD];
__device__ __align__(16) __half g_Kh[(size_t)BB * HH * FF * HD];
__device__ __align__(16) __half g_Vh[(size_t)BB * HH * FF * HD];
// Exact sum-of-V path (fp32)
__device__ float g_srow[(size_t)BB * DD];
__device__ float g_SV  [(size_t)BB * AA];
// Prepacked weights in mma B-fragment order, fp16:
// [p][nt(4)][chunk(8)] blobs of 16KB; blob = [kstep(4)][nb(16)][lane(32)][reg(2)] u32
__device__ uint32_t g_Wt[(size_t)3 * 4 * 8 * 4096];

// ---------------------------------------------------------------------------
// PTX helpers (baseline ISA only)
// ---------------------------------------------------------------------------
__device__ __forceinline__ uint32_t smem_u32(const void* p) {
    uint32_t a;
    asm("{ .reg .u64 t; cvta.to.shared.u64 t, %1; cvt.u32.u64 %0, t; }" : "=r"(a) : "l"(p));
    return a;
}
__device__ __forceinline__ void ldsm4(uint32_t* r, uint32_t addr) {
    asm volatile("ldmatrix.sync.aligned.m8n8.x4.shared.b16 {%0,%1,%2,%3}, [%4];"
                 : "=r"(r[0]), "=r"(r[1]), "=r"(r[2]), "=r"(r[3]) : "r"(addr));
}
__device__ __forceinline__ void mma16816(float* c, const uint32_t* a, const uint32_t* b) {
    asm volatile(
        "mma.sync.aligned.m16n8k16.row.col.f32.f16.f16.f32 "
        "{%0,%1,%2,%3}, {%4,%5,%6,%7}, {%8,%9}, {%0,%1,%2,%3};"
        : "+f"(c[0]), "+f"(c[1]), "+f"(c[2]), "+f"(c[3])
        : "r"(a[0]), "r"(a[1]), "r"(a[2]), "r"(a[3]), "r"(b[0]), "r"(b[1]));
}
__device__ __forceinline__ void cpasync16(uint32_t dst, const void* src) {
    asm volatile("cp.async.cg.shared.global [%0], [%1], 16;" :: "r"(dst), "l"(src));
}
__device__ __forceinline__ void cp_commit() { asm volatile("cp.async.commit_group;"); }
__device__ __forceinline__ void cp_wait0()  { asm volatile("cp.async.wait_group 0;" ::: "memory"); }

__device__ __forceinline__ uint32_t pack_h2(float a, float b) {
    return (uint32_t)__half_as_ushort(__float2half_rn(a)) |
           ((uint32_t)__half_as_ushort(__float2half_rn(b)) << 16);
}

// ---------------------------------------------------------------------------
// Prepack: W fp32 -> fp16 in mma B-fragment order. grid (8, 4, 3), 256 thr.
// ---------------------------------------------------------------------------
__global__ __launch_bounds__(256) void prepack_kernel(
    const float* __restrict__ Wq, const float* __restrict__ Wk, const float* __restrict__ Wv)
{
    const int c  = blockIdx.x;
    const int nt = blockIdx.y;
    const int p  = blockIdx.z;
    const float* W = (p == 0) ? Wq : (p == 1) ? Wk : Wv;
    uint32_t* dst = g_Wt + (((size_t)p * 4 + nt) * 8 + c) * 4096;

    for (int j = 0; j < 16; j++) {
        int s = threadIdx.x + j * 256;            // 0..4095
        int reg  = s & 1;
        int lane = (s >> 1) & 31;
        int nb   = (s >> 6) & 15;
        int ks   = s >> 10;                       // 0..3
        int k = c * 64 + ks * 16 + 2 * (lane & 3) + 8 * reg;
        int n = nt * 128 + nb * 8 + (lane >> 2);
        float w0 = W[(size_t)k * AA + n];
        float w1 = W[(size_t)(k + 1) * AA + n];
        dst[s] = pack_h2(w0, w1);
    }
}

// ---------------------------------------------------------------------------
// srow[b][d] = sum_f value[b][f][d]   (fp32 exact)
// ---------------------------------------------------------------------------
__global__ __launch_bounds__(128) void srow_kernel(const float* __restrict__ value)
{
    const int b = blockIdx.x;
    const int t = threadIdx.x;
    const float* src = value + (size_t)b * FF * DD + t * 4;
    float4 s = make_float4(0.f, 0.f, 0.f, 0.f);
    #pragma unroll 8
    for (int f = 0; f < FF; f++) {
        float4 v = *reinterpret_cast<const float4*>(src + (size_t)f * DD);
        s.x += v.x; s.y += v.y; s.z += v.z; s.w += v.w;
    }
    *reinterpret_cast<float4*>(g_srow + (size_t)b * DD + t * 4) = s;
}

// ---------------------------------------------------------------------------
// SV[b][n] = srow[b] . Wv[:,n] + 64*bv[n]   (fp32 exact, tiny GEMM)
// ---------------------------------------------------------------------------
__global__ __launch_bounds__(256) void sv_kernel(
    const float* __restrict__ Wv, const float* __restrict__ bv)
{
    const int mt = blockIdx.x;
    const int nt = blockIdx.y;
    __shared__ float As[16][68];
    __shared__ float Bs[16][64];
    const int tid = threadIdx.x;
    const int tx = tid & 15, ty = tid >> 4;

    float acc[4][4];
    #pragma unroll
    for (int i = 0; i < 4; i++)
        #pragma unroll
        for (int j = 0; j < 4; j++) acc[i][j] = 0.f;

    for (int k0 = 0; k0 < DD; k0 += 16) {
        #pragma unroll
        for (int j = 0; j < 4; j++) {
            int e = tid + j * 256;
            int m = e >> 4, kk = e & 15;
            As[kk][m] = g_srow[(size_t)(mt * 64 + m) * DD + k0 + kk];
        }
        #pragma unroll
        for (int j = 0; j < 4; j++) {
            int e = tid + j * 256;
            int kk = e >> 6, n = e & 63;
            Bs[kk][n] = Wv[(size_t)(k0 + kk) * AA + nt * 64 + n];
        }
        __syncthreads();
        #pragma unroll
        for (int kk = 0; kk < 16; kk++) {
            float a[4], b[4];
            #pragma unroll
            for (int i = 0; i < 4; i++) a[i] = As[kk][ty * 4 + i];
            #pragma unroll
            for (int j = 0; j < 4; j++) b[j] = Bs[kk][tx * 4 + j];
            #pragma unroll
            for (int i = 0; i < 4; i++)
                #pragma unroll
                for (int j = 0; j < 4; j++)
                    acc[i][j] = fmaf(a[i], b[j], acc[i][j]);
        }
        __syncthreads();
    }
    #pragma unroll
    for (int i = 0; i < 4; i++)
        #pragma unroll
        for (int j = 0; j < 4; j++) {
            int n = nt * 64 + tx * 4 + j;
            g_SV[(size_t)(mt * 64 + ty * 4 + i) * AA + n] = acc[i][j] + 64.f * bv[n];
        }
}

// ---------------------------------------------------------------------------
// Projection GEMM (mma.sync fp16). grid (4 nt, 2048 b, 3 p), 128 thr (4 warps).
// CTA tile 64(M=one batch) x 128(N) x 512(K in 8 chunks). Warp tile 32x64.
// 4 CTAs/SM: small barriers, cross-CTA overlap. Output fp16 to [b,h,f,d].
// SMEM (51200 B): Xs 2 x 9216 | Bs 2 x 16384.
// Epilogue reuse: fp32 tile 64 x 132 at [0, 33792), s_add at [34816, +512).
// ---------------------------------------------------------------------------
__global__ __launch_bounds__(128, 4) void proj_mma_kernel(
    const float* __restrict__ Xq, const float* __restrict__ Xk, const float* __restrict__ Xv,
    const float* __restrict__ bv)
{
    const int nt = blockIdx.x;
    const int b  = blockIdx.y;
    const int p  = blockIdx.z;
    const float* X   = (p == 0) ? Xq : (p == 1) ? Xk : Xv;
    __half*      dst = (p == 0) ? g_Qh : (p == 1) ? g_Kh : g_Vh;

    extern __shared__ __align__(16) unsigned char smd[];
    const uint32_t sbase = smem_u32(smd);
    const int tid   = threadIdx.x;
    const int lane  = tid & 31;
    const int wid   = tid >> 5;
    const int warpM = wid >> 1;      // 0..1
    const int warpN = wid & 1;       // 0..1

    const float* Xb = X + (size_t)b * FF * DD;
    const uint32_t* Wg = g_Wt + (((size_t)p * 4 + nt) * 8) * 4096;

    float acc[2][8][4];
    #pragma unroll
    for (int mf = 0; mf < 2; mf++)
        #pragma unroll
        for (int nb = 0; nb < 8; nb++)
            #pragma unroll
            for (int r = 0; r < 4; r++) acc[mf][nb][r] = 0.f;

    uint2 xr[8];
    #define LOADX(c) do { \
        _Pragma("unroll") \
        for (int i = 0; i < 8; i++) { \
            int idx = tid + i * 128; \
            int m = idx >> 4, kq = idx & 15; \
            float4 v = *reinterpret_cast<const float4*>(Xb + (size_t)m * DD + (c) * 64 + kq * 4); \
            xr[i].x = pack_h2(v.x, v.y); \
            xr[i].y = pack_h2(v.z, v.w); \
        } } while (0)
    #define STOREX(buf) do { \
        _Pragma("unroll") \
        for (int i = 0; i < 8; i++) { \
            int idx = tid + i * 128; \
            int m = idx >> 4, kq = idx & 15; \
            *reinterpret_cast<uint2*>(smd + (buf) * 9216 + m * 144 + kq * 8) = xr[i]; \
        } } while (0)
    #define CPB(c, buf) do { \
        const char* src = reinterpret_cast<const char*>(Wg + (size_t)(c) * 4096); \
        _Pragma("unroll") \
        for (int i = 0; i < 8; i++) { \
            int off = (tid + i * 128) * 16; \
            cpasync16(sbase + 18432 + (buf) * 16384 + off, src + off); \
        } \
        cp_commit(); } while (0)

    LOADX(0);
    CPB(0, 0);

    for (int c = 0; c < 8; ++c) {
        const int buf = c & 1;
        STOREX(buf);
        cp_wait0();
        __syncthreads();
        if (c < 7) { CPB(c + 1, buf ^ 1); LOADX(c + 1); }

        const uint32_t abase = sbase + buf * 9216;
        #pragma unroll
        for (int ks = 0; ks < 4; ks++) {
            uint32_t a0[4], a1[4];
            uint32_t ad = abase + (warpM * 32 + (lane & 15)) * 144 + ks * 32 + (lane >> 4) * 16;
            ldsm4(a0, ad);
            ldsm4(a1, ad + 16 * 144);
            #pragma unroll
            for (int nb = 0; nb < 8; nb++) {
                uint2 bb = *reinterpret_cast<const uint2*>(
                    smd + 18432 + buf * 16384 +
                    (((ks * 16) + warpN * 8 + nb) * 32 + lane) * 8);
                mma16816(acc[0][nb], a0, &bb.x);
                mma16816(acc[1][nb], a1, &bb.x);
            }
        }
        __syncthreads();
    }

    // ---- epilogue ----
    float* tile  = reinterpret_cast<float*>(smd);          // 64 x 132
    float* s_add = reinterpret_cast<float*>(smd + 34816);  // [128]
    #pragma unroll
    for (int mf = 0; mf < 2; mf++) {
        #pragma unroll
        for (int nb = 0; nb < 8; nb++) {
            int row = warpM * 32 + mf * 16 + (lane >> 2);
            int col = warpN * 64 + nb * 8 + 2 * (lane & 3);
            *reinterpret_cast<float2*>(&tile[row * 132 + col]) =
                make_float2(acc[mf][nb][0], acc[mf][nb][1]);
            *reinterpret_cast<float2*>(&tile[(row + 8) * 132 + col]) =
                make_float2(acc[mf][nb][2], acc[mf][nb][3]);
        }
    }
    __syncthreads();

    {
        int col = tid;                            // 0..127
        if (p < 2) {
            float s = 0.f;
            #pragma unroll 8
            for (int r = 0; r < 64; r++) s += tile[r * 132 + col];
            s_add[col] = -s * (1.f / 64.f);
        } else {
            s_add[col] = bv[nt * 128 + col];
        }
    }
    __syncthreads();

    // write fp16 to [b,h,f,d]
    #pragma unroll 4
    for (int i = 0; i < 16; i++) {
        int id = tid + i * 128;          // 0..2047 float4 groups
        int r  = id >> 5;                // 0..63
        int cq = id & 31;                // 0..31
        float4 v = *reinterpret_cast<const float4*>(&tile[r * 132 + cq * 4]);
        const float* ad = &s_add[cq * 4];
        v.x += ad[0]; v.y += ad[1]; v.z += ad[2]; v.w += ad[3];
        int n0 = nt * 128 + cq * 4;
        int h  = n0 >> 6;
        int d0 = n0 & 63;
        uint2 hv = make_uint2(pack_h2(v.x, v.y), pack_h2(v.z, v.w));
        *reinterpret_cast<uint2*>(dst + (((size_t)b * HH + h) * FF + r) * HD + d0) = hv;
    }
}

// ---------------------------------------------------------------------------
// Attention per (b,h): S = Qc Kc^T, P = softmax(S) (exact SV added in the
// epilogue instead of +1), O = P V + SV + query, relu.
// 128 threads = 2 heads x 64 threads, 8x8 microtiles, interleaved ownership.
// Scratch inputs are fp16 (uint4 loads -> cvt -> fp32 smem compute).
// ---------------------------------------------------------------------------
__global__ __launch_bounds__(128) void attn_kernel(
    const float* __restrict__ query, float* __restrict__ out)
{
    const int hs   = threadIdx.x >> 6;
    const int htid = threadIdx.x & 63;
    const int bh = blockIdx.x * 2 + hs;
    const int b  = bh >> 3;
    const int h  = bh & 7;

    extern __shared__ float sm[];
    float* Qs = sm + hs * 3 * 64 * 68;        // later reused as Vt [d][f]
    float* Ks = Qs + 64 * 68;
    float* Ss = Qs + 2 * 64 * 68;

    const int tx = htid & 7;
    const int ty = htid >> 3;

    const __half* Qg = g_Qh + (size_t)bh * FF * HD;
    const __half* Kg = g_Kh + (size_t)bh * FF * HD;
    const __half* Vg = g_Vh + (size_t)bh * FF * HD;

    // Load Qc, Kc: 8 uint4 (8 halves) per thread per tile.
    {
        const int dv8 = htid & 7;                // uint4 col group (8 halves)
        const int f0  = htid >> 3;               // 0..7
        #pragma unroll
        for (int i = 0; i < 8; i++) {
            int f = f0 + i * 8;
            uint4 q = *reinterpret_cast<const uint4*>(Qg + f * 64 + dv8 * 8);
            uint4 k = *reinterpret_cast<const uint4*>(Kg + f * 64 + dv8 * 8);
            const __half2* qh = reinterpret_cast<const __half2*>(&q);
            const __half2* kh = reinterpret_cast<const __half2*>(&k);
            #pragma unroll
            for (int j = 0; j < 4; j++) {
                float2 qf = __half22float2(qh[j]);
                float2 kf = __half22float2(kh[j]);
                Qs[f * 68 + dv8 * 8 + 2 * j]     = qf.x;
                Qs[f * 68 + dv8 * 8 + 2 * j + 1] = qf.y;
                Ks[f * 68 + dv8 * 8 + 2 * j]     = kf.x;
                Ks[f * 68 + dv8 * 8 + 2 * j + 1] = kf.y;
            }
        }
    }
    __syncthreads();

    // S = Qc @ Kc^T, 8x8 per thread, interleaved (stride 8)
    float s[8][8];
    #pragma unroll
    for (int i = 0; i < 8; i++)
        #pragma unroll
        for (int j = 0; j < 8; j++) s[i][j] = 0.f;

    #pragma unroll 4
    for (int d = 0; d < 64; d += 4) {
        float4 a[8], c[8];
        #pragma unroll
        for (int i = 0; i < 8; i++) a[i] = *reinterpret_cast<const float4*>(Qs + (ty + 8 * i) * 68 + d);
        #pragma unroll
        for (int j = 0; j < 8; j++) c[j] = *reinterpret_cast<const float4*>(Ks + (tx + 8 * j) * 68 + d);
        #pragma unroll
        for (int i = 0; i < 8; i++)
            #pragma unroll
            for (int j = 0; j < 8; j++) {
                s[i][j] = fmaf(a[i].x, c[j].x, s[i][j]);
                s[i][j] = fmaf(a[i].y, c[j].y, s[i][j]);
                s[i][j] = fmaf(a[i].z, c[j].z, s[i][j]);
                s[i][j] = fmaf(a[i].w, c[j].w, s[i][j]);
            }
    }
    #pragma unroll
    for (int i = 0; i < 8; i++)
        #pragma unroll
        for (int j = 0; j < 8; j++)
            Ss[(ty + 8 * i) * 68 + tx + 8 * j] = s[i][j];
    __syncthreads();

    // Load V transposed into Qs: Vt[d][f]
    {
        const int dv8 = htid & 7;
        const int f0  = htid >> 3;
        #pragma unroll
        for (int i = 0; i < 8; i++) {
            int f = f0 + i * 8;
            uint4 v = *reinterpret_cast<const uint4*>(Vg + f * 64 + dv8 * 8);
            const __half2* vh = reinterpret_cast<const __half2*>(&v);
            #pragma unroll
            for (int j = 0; j < 4; j++) {
                float2 vf = __half22float2(vh[j]);
                Qs[(dv8 * 8 + 2 * j) * 68 + f]     = vf.x;
                Qs[(dv8 * 8 + 2 * j + 1) * 68 + f] = vf.y;
            }
        }
    }

    // Row softmax (one row per thread)
    {
        float* row = Ss + htid * 68;
        float4 e[16];
        float mx = -INFINITY;
        #pragma unroll
        for (int j = 0; j < 16; j++) {
            e[j] = *reinterpret_cast<const float4*>(row + j * 4);
            mx = fmaxf(mx, fmaxf(fmaxf(e[j].x, e[j].y), fmaxf(e[j].z, e[j].w)));
        }
        float sum = 0.f;
        #pragma unroll
        for (int j = 0; j < 16; j++) {
            e[j].x = __expf(e[j].x - mx); e[j].y = __expf(e[j].y - mx);
            e[j].z = __expf(e[j].z - mx); e[j].w = __expf(e[j].w - mx);
            sum += e[j].x + e[j].y + e[j].z + e[j].w;
        }
        float inv = 1.f / sum;
        #pragma unroll
        for (int j = 0; j < 16; j++) {
            e[j].x *= inv; e[j].y *= inv; e[j].z *= inv; e[j].w *= inv;
            *reinterpret_cast<float4*>(row + j * 4) = e[j];
        }
    }
    __syncthreads();

    // O = P @ V via Vt
    float o[8][8];
    #pragma unroll
    for (int i = 0; i < 8; i++)
        #pragma unroll
        for (int j = 0; j < 8; j++) o[i][j] = 0.f;

    #pragma unroll 4
    for (int k = 0; k < 64; k += 4) {
        float4 pr[8], v[8];
        #pragma unroll
        for (int i = 0; i < 8; i++) pr[i] = *reinterpret_cast<const float4*>(Ss + (ty + 8 * i) * 68 + k);
        #pragma unroll
        for (int j = 0; j < 8; j++) v[j] = *reinterpret_cast<const float4*>(Qs + (tx + 8 * j) * 68 + k);
        #pragma unroll
        for (int i = 0; i < 8; i++)
            #pragma unroll
            for (int j = 0; j < 8; j++) {
                o[i][j] = fmaf(pr[i].x, v[j].x, o[i][j]);
                o[i][j] = fmaf(pr[i].y, v[j].y, o[i][j]);
                o[i][j] = fmaf(pr[i].z, v[j].z, o[i][j]);
                o[i][j] = fmaf(pr[i].w, v[j].w, o[i][j]);
            }
    }
    __syncthreads();

    // Re-layout O through Ss for vectorized global stores
    #pragma unroll
    for (int i = 0; i < 8; i++)
        #pragma unroll
        for (int j = 0; j < 8; j++)
            Ss[(ty + 8 * i) * 68 + tx + 8 * j] = o[i][j];
    __syncthreads();

    // Epilogue: out = relu(O + SV + query)
    {
        const int dv = htid & 15;
        const int f0 = htid >> 4;
        float4 sv4 = *reinterpret_cast<const float4*>(g_SV + (size_t)b * AA + h * HD + dv * 4);
        const float* qry = query + (size_t)b * FF * (HH * HD) + h * HD + dv * 4;
        float*       ob  = out   + (size_t)b * FF * (HH * HD) + h * HD + dv * 4;
        #pragma unroll
        for (int i = 0; i < 16; i++) {
            int f = f0 + i * 4;
            float4 ov = *reinterpret_cast<const float4*>(Ss + f * 68 + dv * 4);
            float4 qv = *reinterpret_cast<const float4*>(qry + (size_t)f * (HH * HD));
            float4 r;
            r.x = fmaxf(ov.x + sv4.x + qv.x, 0.f);
            r.y = fmaxf(ov.y + sv4.y + qv.y, 0.f);
            r.z = fmaxf(ov.z + sv4.z + qv.z, 0.f);
            r.w = fmaxf(ov.w + sv4.w + qv.w, 0.f);
            *reinterpret_cast<float4*>(ob + (size_t)f * (HH * HD)) = r;
        }
    }
}

// ---------------------------------------------------------------------------
extern "C" void kernel_launch(void* const* d_in, const int* in_sizes, int n_in,
                              void* d_out, int out_size)
{
    const float* query = (const float*)d_in[0];
    const float* key   = (const float*)d_in[1];
    const float* value = (const float*)d_in[2];
    const float* Wq    = (const float*)d_in[3];
    // d_in[4] (bq), d_in[6] (bk): cancel exactly under mean-centering.
    const float* Wk    = (const float*)d_in[5];
    const float* Wv    = (const float*)d_in[7];
    const float* bv    = (const float*)d_in[8];
    // d_in[9]/d_in[10] (Wk2/bk2) unused: unary softmax over size-1 axis == 1.
    float* out = (float*)d_out;

    prepack_kernel<<<dim3(8, 4, 3), 256>>>(Wq, Wk, Wv);
    srow_kernel<<<BB, 128>>>(value);
    sv_kernel<<<dim3(32, 8), 256>>>(Wv, bv);

    const int proj_smem = 51200;
    cudaFuncSetAttribute(proj_mma_kernel, cudaFuncAttributeMaxDynamicSharedMemorySize, proj_smem);
    proj_mma_kernel<<<dim3(4, BB, 3), 128, proj_smem>>>(query, key, value, bv);

    const int attn_smem = 2 * 3 * 64 * 68 * (int)sizeof(float);  // 104448
    cudaFuncSetAttribute(attn_kernel, cudaFuncAttributeMaxDynamicSharedMemorySize, attn_smem);
    attn_kernel<<<BB * HH / 2, 128, attn_smem>>>(query, out);
}

// round 8
// speedup vs baseline: 4.2938x; 1.2972x over previous
#include <cuda_runtime.h>
#include <cuda_fp16.h>
#include <math.h>
#include <stdint.h>

#define BB 2048
#define FF 64
#define DD 512
#define AA 512
#define HH 8
#define HD 64

// Exact sum-of-V path (fp32)
__device__ float g_srow[(size_t)BB * DD];
__device__ float g_SV  [(size_t)BB * AA];
// Prepacked weights in mma B-fragment order, fp16:
// [p][nt(4)][chunk(8)] blobs of 16KB; blob = [kstep(4)][nb(16)][lane(32)][reg(2)] u32
__device__ uint32_t g_Wt[(size_t)3 * 4 * 8 * 4096];

// ---------------------------------------------------------------------------
// PTX helpers (baseline ISA only)
// ---------------------------------------------------------------------------
__device__ __forceinline__ uint32_t smem_u32(const void* p) {
    uint32_t a;
    asm("{ .reg .u64 t; cvta.to.shared.u64 t, %1; cvt.u32.u64 %0, t; }" : "=r"(a) : "l"(p));
    return a;
}
__device__ __forceinline__ void ldsm4(uint32_t* r, uint32_t addr) {
    asm volatile("ldmatrix.sync.aligned.m8n8.x4.shared.b16 {%0,%1,%2,%3}, [%4];"
                 : "=r"(r[0]), "=r"(r[1]), "=r"(r[2]), "=r"(r[3]) : "r"(addr));
}
__device__ __forceinline__ void mma16816(float* c, const uint32_t* a, const uint32_t* b) {
    asm volatile(
        "mma.sync.aligned.m16n8k16.row.col.f32.f16.f16.f32 "
        "{%0,%1,%2,%3}, {%4,%5,%6,%7}, {%8,%9}, {%0,%1,%2,%3};"
        : "+f"(c[0]), "+f"(c[1]), "+f"(c[2]), "+f"(c[3])
        : "r"(a[0]), "r"(a[1]), "r"(a[2]), "r"(a[3]), "r"(b[0]), "r"(b[1]));
}
__device__ __forceinline__ void cpasync16(uint32_t dst, const void* src) {
    asm volatile("cp.async.cg.shared.global [%0], [%1], 16;" :: "r"(dst), "l"(src));
}
__device__ __forceinline__ void cp_commit() { asm volatile("cp.async.commit_group;"); }
__device__ __forceinline__ void cp_wait0()  { asm volatile("cp.async.wait_group 0;" ::: "memory"); }

__device__ __forceinline__ uint32_t pack_h2(float a, float b) {
    return (uint32_t)__half_as_ushort(__float2half_rn(a)) |
           ((uint32_t)__half_as_ushort(__float2half_rn(b)) << 16);
}

// ---------------------------------------------------------------------------
// Prepack: W fp32 -> fp16 in mma B-fragment order. grid (8, 4, 3), 256 thr.
// ---------------------------------------------------------------------------
__global__ __launch_bounds__(256) void prepack_kernel(
    const float* __restrict__ Wq, const float* __restrict__ Wk, const float* __restrict__ Wv)
{
    const int c  = blockIdx.x;
    const int nt = blockIdx.y;
    const int p  = blockIdx.z;
    const float* W = (p == 0) ? Wq : (p == 1) ? Wk : Wv;
    uint32_t* dst = g_Wt + (((size_t)p * 4 + nt) * 8 + c) * 4096;

    for (int j = 0; j < 16; j++) {
        int s = threadIdx.x + j * 256;            // 0..4095
        int reg  = s & 1;
        int lane = (s >> 1) & 31;
        int nb   = (s >> 6) & 15;
        int ks   = s >> 10;                       // 0..3
        int k = c * 64 + ks * 16 + 2 * (lane & 3) + 8 * reg;
        int n = nt * 128 + nb * 8 + (lane >> 2);
        float w0 = W[(size_t)k * AA + n];
        float w1 = W[(size_t)(k + 1) * AA + n];
        dst[s] = pack_h2(w0, w1);
    }
}

// ---------------------------------------------------------------------------
// srow[b][d] = sum_f value[b][f][d]   (fp32 exact)
// ---------------------------------------------------------------------------
__global__ __launch_bounds__(128) void srow_kernel(const float* __restrict__ value)
{
    const int b = blockIdx.x;
    const int t = threadIdx.x;
    const float* src = value + (size_t)b * FF * DD + t * 4;
    float4 s = make_float4(0.f, 0.f, 0.f, 0.f);
    #pragma unroll 8
    for (int f = 0; f < FF; f++) {
        float4 v = *reinterpret_cast<const float4*>(src + (size_t)f * DD);
        s.x += v.x; s.y += v.y; s.z += v.z; s.w += v.w;
    }
    *reinterpret_cast<float4*>(g_srow + (size_t)b * DD + t * 4) = s;
}

// ---------------------------------------------------------------------------
// SV[b][n] = srow[b] . Wv[:,n] + 64*bv[n]   (fp32 exact, tiny GEMM)
// ---------------------------------------------------------------------------
__global__ __launch_bounds__(256) void sv_kernel(
    const float* __restrict__ Wv, const float* __restrict__ bv)
{
    const int mt = blockIdx.x;
    const int nt = blockIdx.y;
    __shared__ float As[16][68];
    __shared__ float Bs[16][64];
    const int tid = threadIdx.x;
    const int tx = tid & 15, ty = tid >> 4;

    float acc[4][4];
    #pragma unroll
    for (int i = 0; i < 4; i++)
        #pragma unroll
        for (int j = 0; j < 4; j++) acc[i][j] = 0.f;

    for (int k0 = 0; k0 < DD; k0 += 16) {
        #pragma unroll
        for (int j = 0; j < 4; j++) {
            int e = tid + j * 256;
            int m = e >> 4, kk = e & 15;
            As[kk][m] = g_srow[(size_t)(mt * 64 + m) * DD + k0 + kk];
        }
        #pragma unroll
        for (int j = 0; j < 4; j++) {
            int e = tid + j * 256;
            int kk = e >> 6, n = e & 63;
            Bs[kk][n] = Wv[(size_t)(k0 + kk) * AA + nt * 64 + n];
        }
        __syncthreads();
        #pragma unroll
        for (int kk = 0; kk < 16; kk++) {
            float a[4], b[4];
            #pragma unroll
            for (int i = 0; i < 4; i++) a[i] = As[kk][ty * 4 + i];
            #pragma unroll
            for (int j = 0; j < 4; j++) b[j] = Bs[kk][tx * 4 + j];
            #pragma unroll
            for (int i = 0; i < 4; i++)
                #pragma unroll
                for (int j = 0; j < 4; j++)
                    acc[i][j] = fmaf(a[i], b[j], acc[i][j]);
        }
        __syncthreads();
    }
    #pragma unroll
    for (int i = 0; i < 4; i++)
        #pragma unroll
        for (int j = 0; j < 4; j++) {
            int n = nt * 64 + tx * 4 + j;
            g_SV[(size_t)(mt * 64 + ty * 4 + i) * AA + n] = acc[i][j] + 64.f * bv[n];
        }
}

// ---------------------------------------------------------------------------
// FUSED kernel: per CTA (nt, b) compute Qc/Kc/V (64 x 128, heads 2nt,2nt+1)
// via HMMA GEMMs into SMEM fp16 tiles, then S = Qc Kc^T, softmax on
// fragments, O = P V via HMMA, epilogue out = relu(O + SV + query).
// 128 threads (4 warps). SMEM 104448 B:
//   XS  [0, 18432)      2 bufs x 64 rows x 144 B fp16
//   BS  [18432, 51200)  2 bufs x 16 KB W fragment blobs
//   QT  [51200, +17408) 64 f-rows x 272 B (128 fp16 cols = 2 heads x 64 d)
//   KT  [68608, +17408) same
//   VT  [86016, +17408) 64 d-rows x 272 B (2 heads x 64 f fp16)
//   RED [103424, +1024) 2 x 128 fp32 column partial sums
// ---------------------------------------------------------------------------
#define XS_OFF 0
#define BS_OFF 18432
#define QT_OFF 51200
#define KT_OFF 68608
#define VT_OFF 86016
#define RED_OFF 103424

__global__ __launch_bounds__(128) void fused_kernel(
    const float* __restrict__ Xq, const float* __restrict__ Xk, const float* __restrict__ Xv,
    const float* __restrict__ bv, const float* __restrict__ query, float* __restrict__ out)
{
    const int nt = blockIdx.x;
    const int b  = blockIdx.y;

    extern __shared__ __align__(16) unsigned char smd[];
    const uint32_t sbase = smem_u32(smd);
    const int tid   = threadIdx.x;
    const int lane  = tid & 31;
    const int wid   = tid >> 5;
    const int warpM = wid >> 1;      // 0..1
    const int warpN = wid & 1;       // 0..1

    float* red = reinterpret_cast<float*>(smd + RED_OFF);   // [2][128]

    // ======================= three GEMMs: p = 0(Q),1(K),2(V) ================
    #pragma unroll 1
    for (int p = 0; p < 3; ++p) {
        const float* Xb = ((p == 0) ? Xq : (p == 1) ? Xk : Xv) + (size_t)b * FF * DD;
        const uint32_t* Wg = g_Wt + (((size_t)p * 4 + nt) * 8) * 4096;

        float acc[2][8][4];
        #pragma unroll
        for (int mf = 0; mf < 2; mf++)
            #pragma unroll
            for (int nb = 0; nb < 8; nb++)
                #pragma unroll
                for (int r = 0; r < 4; r++) acc[mf][nb][r] = 0.f;

        uint2 xr[8];
        #define LOADX(c) do { \
            _Pragma("unroll") \
            for (int i = 0; i < 8; i++) { \
                int idx = tid + i * 128; \
                int m = idx >> 4, kq = idx & 15; \
                float4 v = *reinterpret_cast<const float4*>(Xb + (size_t)m * DD + (c) * 64 + kq * 4); \
                xr[i].x = pack_h2(v.x, v.y); \
                xr[i].y = pack_h2(v.z, v.w); \
            } } while (0)
        #define STOREX(buf) do { \
            _Pragma("unroll") \
            for (int i = 0; i < 8; i++) { \
                int idx = tid + i * 128; \
                int m = idx >> 4, kq = idx & 15; \
                *reinterpret_cast<uint2*>(smd + XS_OFF + (buf) * 9216 + m * 144 + kq * 8) = xr[i]; \
            } } while (0)
        #define CPB(c, buf) do { \
            const char* src = reinterpret_cast<const char*>(Wg + (size_t)(c) * 4096); \
            _Pragma("unroll") \
            for (int i = 0; i < 8; i++) { \
                int off = (tid + i * 128) * 16; \
                cpasync16(sbase + BS_OFF + (buf) * 16384 + off, src + off); \
            } \
            cp_commit(); } while (0)

        LOADX(0);
        CPB(0, 0);

        for (int c = 0; c < 8; ++c) {
            const int buf = c & 1;
            STOREX(buf);
            cp_wait0();
            __syncthreads();
            if (c < 7) { CPB(c + 1, buf ^ 1); LOADX(c + 1); }

            const uint32_t abase = sbase + XS_OFF + buf * 9216;
            #pragma unroll
            for (int ks = 0; ks < 4; ks++) {
                uint32_t a0[4], a1[4];
                uint32_t ad = abase + (warpM * 32 + (lane & 15)) * 144 + ks * 32 + (lane >> 4) * 16;
                ldsm4(a0, ad);
                ldsm4(a1, ad + 16 * 144);
                #pragma unroll
                for (int nb = 0; nb < 8; nb++) {
                    uint2 bb = *reinterpret_cast<const uint2*>(
                        smd + BS_OFF + buf * 16384 +
                        (((ks * 16) + warpN * 8 + nb) * 32 + lane) * 8);
                    mma16816(acc[0][nb], a0, &bb.x);
                    mma16816(acc[1][nb], a1, &bb.x);
                }
            }
            __syncthreads();
        }
        #undef LOADX
        #undef STOREX
        #undef CPB

        // --------------------- epilogue for projection p --------------------
        // acc element map: row = warpM*32 + mf*16 + (lane>>2) + 8*(r>>1),
        //                  col = warpN*64 + nb*8 + 2*(lane&3) + (r&1)
        if (p < 2) {
            // column sums -> RED, then center, store fp16 to QT/KT [f][nloc]
            unsigned char* tilep = smd + ((p == 0) ? QT_OFF : KT_OFF);
            float cs[8][2];
            #pragma unroll
            for (int nb = 0; nb < 8; nb++) {
                cs[nb][0] = acc[0][nb][0] + acc[0][nb][2] + acc[1][nb][0] + acc[1][nb][2];
                cs[nb][1] = acc[0][nb][1] + acc[0][nb][3] + acc[1][nb][1] + acc[1][nb][3];
                #pragma unroll
                for (int d = 4; d <= 16; d <<= 1) {
                    cs[nb][0] += __shfl_xor_sync(0xFFFFFFFFu, cs[nb][0], d);
                    cs[nb][1] += __shfl_xor_sync(0xFFFFFFFFu, cs[nb][1], d);
                }
            }
            if ((lane >> 2) == 0) {
                #pragma unroll
                for (int nb = 0; nb < 8; nb++) {
                    int col = warpN * 64 + nb * 8 + 2 * (lane & 3);
                    *reinterpret_cast<float2*>(&red[warpM * 128 + col]) =
                        make_float2(cs[nb][0], cs[nb][1]);
                }
            }
            __syncthreads();
            #pragma unroll
            for (int nb = 0; nb < 8; nb++) {
                int col = warpN * 64 + nb * 8 + 2 * (lane & 3);
                float m0 = (red[col]     + red[128 + col])     * (1.f / 64.f);
                float m1 = (red[col + 1] + red[128 + col + 1]) * (1.f / 64.f);
                #pragma unroll
                for (int mf = 0; mf < 2; mf++) {
                    int row0 = warpM * 32 + mf * 16 + (lane >> 2);
                    *reinterpret_cast<uint32_t*>(tilep + row0 * 272 + col * 2) =
                        pack_h2(acc[mf][nb][0] - m0, acc[mf][nb][1] - m1);
                    *reinterpret_cast<uint32_t*>(tilep + (row0 + 8) * 272 + col * 2) =
                        pack_h2(acc[mf][nb][2] - m0, acc[mf][nb][3] - m1);
                }
            }
            __syncthreads();
        } else {
            // V: +bv, store TRANSPOSED into VT [d][h*64 + f] (head = warpN)
            unsigned char* vtp = smd + VT_OFF;
            #pragma unroll
            for (int nb = 0; nb < 8; nb++) {
                int col = warpN * 64 + nb * 8 + 2 * (lane & 3);
                float2 bb = *reinterpret_cast<const float2*>(&bv[nt * 128 + col]);
                int d0 = nb * 8 + 2 * (lane & 3);
                #pragma unroll
                for (int mf = 0; mf < 2; mf++) {
                    int row0 = warpM * 32 + mf * 16 + (lane >> 2);
                    *reinterpret_cast<__half*>(vtp + d0 * 272 + warpN * 128 + row0 * 2) =
                        __float2half_rn(acc[mf][nb][0] + bb.x);
                    *reinterpret_cast<__half*>(vtp + (d0 + 1) * 272 + warpN * 128 + row0 * 2) =
                        __float2half_rn(acc[mf][nb][1] + bb.y);
                    *reinterpret_cast<__half*>(vtp + d0 * 272 + warpN * 128 + (row0 + 8) * 2) =
                        __float2half_rn(acc[mf][nb][2] + bb.x);
                    *reinterpret_cast<__half*>(vtp + (d0 + 1) * 272 + warpN * 128 + (row0 + 8) * 2) =
                        __float2half_rn(acc[mf][nb][3] + bb.y);
                }
            }
            __syncthreads();
        }
    }

    // =========================== attention phase ============================
    // warp w: head h = w>>1 (local), row half mh = w&1 (f rows 32*mh..+31)
    const int h  = wid >> 1;
    const int mh = wid & 1;
    const uint32_t qtb = sbase + QT_OFF;
    const uint32_t ktb = sbase + KT_OFF;
    const uint32_t vtb = sbase + VT_OFF;

    // ---- S = Qc @ Kc^T : per warp 32(f) x 64(fk), fp32 accs ----
    float s[2][8][4];
    #pragma unroll
    for (int mt = 0; mt < 2; mt++)
        #pragma unroll
        for (int nb = 0; nb < 8; nb++)
            #pragma unroll
            for (int r = 0; r < 4; r++) s[mt][nb][r] = 0.f;

    #pragma unroll
    for (int ks = 0; ks < 4; ks++) {
        uint32_t a[2][4];
        #pragma unroll
        for (int mt = 0; mt < 2; mt++)
            ldsm4(a[mt], qtb + (mh * 32 + mt * 16 + (lane & 15)) * 272 + h * 128 +
                          ks * 32 + (lane >> 4) * 16);
        uint32_t bq[4][4];
        #pragma unroll
        for (int nq = 0; nq < 4; nq++)
            ldsm4(bq[nq], ktb + (nq * 16 + (lane & 15)) * 272 + h * 128 +
                           ks * 32 + (lane >> 4) * 16);
        #pragma unroll
        for (int mt = 0; mt < 2; mt++) {
            #pragma unroll
            for (int nq = 0; nq < 4; nq++) {
                uint32_t b0[2] = {bq[nq][0], bq[nq][2]};
                uint32_t b1[2] = {bq[nq][1], bq[nq][3]};
                mma16816(s[mt][2 * nq],     a[mt], b0);
                mma16816(s[mt][2 * nq + 1], a[mt], b1);
            }
        }
    }

    // ---- softmax on fragments: rows = (mt, hi); cols across nb + lane&3 ----
    #pragma unroll
    for (int mt = 0; mt < 2; mt++) {
        #pragma unroll
        for (int hi = 0; hi < 2; hi++) {
            float mx = -INFINITY;
            #pragma unroll
            for (int nb = 0; nb < 8; nb++)
                mx = fmaxf(mx, fmaxf(s[mt][nb][2 * hi], s[mt][nb][2 * hi + 1]));
            mx = fmaxf(mx, __shfl_xor_sync(0xFFFFFFFFu, mx, 1));
            mx = fmaxf(mx, __shfl_xor_sync(0xFFFFFFFFu, mx, 2));
            float sum = 0.f;
            #pragma unroll
            for (int nb = 0; nb < 8; nb++) {
                float e0 = __expf(s[mt][nb][2 * hi]     - mx);
                float e1 = __expf(s[mt][nb][2 * hi + 1] - mx);
                s[mt][nb][2 * hi] = e0; s[mt][nb][2 * hi + 1] = e1;
                sum += e0 + e1;
            }
            sum += __shfl_xor_sync(0xFFFFFFFFu, sum, 1);
            sum += __shfl_xor_sync(0xFFFFFFFFu, sum, 2);
            float inv = 1.f / sum;
            #pragma unroll
            for (int nb = 0; nb < 8; nb++) {
                s[mt][nb][2 * hi]     *= inv;
                s[mt][nb][2 * hi + 1] *= inv;
            }
        }
    }

    // ---- O = P @ V : P accs -> A fragments in registers; B from VT ----
    float o[2][8][4];
    #pragma unroll
    for (int mt = 0; mt < 2; mt++)
        #pragma unroll
        for (int nb = 0; nb < 8; nb++)
            #pragma unroll
            for (int r = 0; r < 4; r++) o[mt][nb][r] = 0.f;

    #pragma unroll
    for (int kt = 0; kt < 4; kt++) {
        uint32_t pa[2][4];
        #pragma unroll
        for (int mt = 0; mt < 2; mt++) {
            pa[mt][0] = pack_h2(s[mt][2 * kt][0],     s[mt][2 * kt][1]);
            pa[mt][1] = pack_h2(s[mt][2 * kt][2],     s[mt][2 * kt][3]);
            pa[mt][2] = pack_h2(s[mt][2 * kt + 1][0], s[mt][2 * kt + 1][1]);
            pa[mt][3] = pack_h2(s[mt][2 * kt + 1][2], s[mt][2 * kt + 1][3]);
        }
        uint32_t bq[4][4];
        #pragma unroll
        for (int nq = 0; nq < 4; nq++)
            ldsm4(bq[nq], vtb + (nq * 16 + (lane & 15)) * 272 + h * 128 +
                           kt * 32 + (lane >> 4) * 16);
        #pragma unroll
        for (int mt = 0; mt < 2; mt++) {
            #pragma unroll
            for (int nq = 0; nq < 4; nq++) {
                uint32_t b0[2] = {bq[nq][0], bq[nq][2]};
                uint32_t b1[2] = {bq[nq][1], bq[nq][3]};
                mma16816(o[mt][2 * nq],     pa[mt], b0);
                mma16816(o[mt][2 * nq + 1], pa[mt], b1);
            }
        }
    }

    // ---- epilogue: out = relu(O + SV + query), head cols (2nt+h)*64 ----
    const int hg = 2 * nt + h;
    const float* svp = g_SV + (size_t)b * AA + hg * 64;
    const float* qp  = query + (size_t)b * FF * AA + hg * 64;
    float*       op  = out   + (size_t)b * FF * AA + hg * 64;
    #pragma unroll
    for (int mt = 0; mt < 2; mt++) {
        #pragma unroll
        for (int nb = 0; nb < 8; nb++) {
            int d = nb * 8 + 2 * (lane & 3);
            float2 sv = *reinterpret_cast<const float2*>(svp + d);
            #pragma unroll
            for (int hi = 0; hi < 2; hi++) {
                int f = 32 * mh + mt * 16 + (lane >> 2) + 8 * hi;
                float2 q = *reinterpret_cast<const float2*>(qp + (size_t)f * AA + d);
                float2 r;
                r.x = fmaxf(o[mt][nb][2 * hi]     + sv.x + q.x, 0.f);
                r.y = fmaxf(o[mt][nb][2 * hi + 1] + sv.y + q.y, 0.f);
                *reinterpret_cast<float2*>(op + (size_t)f * AA + d) = r;
            }
        }
    }
}

// ---------------------------------------------------------------------------
extern "C" void kernel_launch(void* const* d_in, const int* in_sizes, int n_in,
                              void* d_out, int out_size)
{
    const float* query = (const float*)d_in[0];
    const float* key   = (const float*)d_in[1];
    const float* value = (const float*)d_in[2];
    const float* Wq    = (const float*)d_in[3];
    // d_in[4] (bq), d_in[6] (bk): cancel exactly under mean-centering.
    const float* Wk    = (const float*)d_in[5];
    const float* Wv    = (const float*)d_in[7];
    const float* bv    = (const float*)d_in[8];
    // d_in[9]/d_in[10] (Wk2/bk2) unused: unary softmax over size-1 axis == 1.
    float* out = (float*)d_out;

    prepack_kernel<<<dim3(8, 4, 3), 256>>>(Wq, Wk, Wv);
    srow_kernel<<<BB, 128>>>(value);
    sv_kernel<<<dim3(32, 8), 256>>>(Wv, bv);

    const int fused_smem = 104448;
    cudaFuncSetAttribute(fused_kernel, cudaFuncAttributeMaxDynamicSharedMemorySize, fused_smem);
    fused_kernel<<<dim3(4, BB), 128, fused_smem>>>(query, key, value, bv, query, out);
}